// round 8
// baseline (speedup 1.0000x reference)
#include <cuda_runtime.h>

#define NN 100000
#define EE 1600000

// ---------------- scratch (static device globals; no allocation) ------------
__device__ float  g_h[NN * 128];       // node features, updated in place
__device__ float2 g_hblkA[NN * 32];    // ping-pong relu(LN(half)) buffers
__device__ float2 g_hblkB[NN * 32];
__device__ int    g_cnt[NN];           // zero-init; re-zeroed by k_scan each run
__device__ int    g_off[NN + 1];
__device__ int    g_cur[NN];
__device__ int    g_srcp[EE];          // src permuted by dst
__device__ float  g_eap[EE * 8];       // edge_attr permuted by dst
__device__ float  g_wc[4 * 8 * 64];    // folded W_ee @ We per block
__device__ float  g_bc[4 * 64];        // folded bias per block

// ---------------- histogram ---------------------------------------------------
__global__ void k_hist(const int* __restrict__ dst) {
    int i = blockIdx.x * blockDim.x + threadIdx.x;
    if (i < EE) atomicAdd(&g_cnt[dst[i]], 1);
}

// ------- scan: 4 elems/thread, 25 serial chunks; re-zeroes g_cnt ------------
__global__ void k_scan() {
    __shared__ int wsum[32];
    __shared__ int s_carry;
    int tid = threadIdx.x, lane = tid & 31, wid = tid >> 5;
    if (tid == 0) s_carry = 0;
    __syncthreads();
    for (int base = 0; base < NN; base += 4096) {
        int i0 = base + tid * 4;
        int v[4];
        #pragma unroll
        for (int u = 0; u < 4; u++) {
            int i = i0 + u;
            v[u] = (i < NN) ? g_cnt[i] : 0;
            if (i < NN) g_cnt[i] = 0;
        }
        int tsum = v[0] + v[1] + v[2] + v[3];
        int x = tsum;
        #pragma unroll
        for (int d = 1; d < 32; d <<= 1) {
            int t = __shfl_up_sync(0xffffffffu, x, d);
            if (lane >= d) x += t;
        }
        if (lane == 31) wsum[wid] = x;
        __syncthreads();
        if (wid == 0) {
            int w = wsum[lane];
            #pragma unroll
            for (int d = 1; d < 32; d <<= 1) {
                int t = __shfl_up_sync(0xffffffffu, w, d);
                if (lane >= d) w += t;
            }
            wsum[lane] = w;
        }
        __syncthreads();
        int carry = s_carry;
        int run = x - tsum + ((wid > 0) ? wsum[wid - 1] : 0) + carry;
        #pragma unroll
        for (int u = 0; u < 4; u++) {
            int i = i0 + u;
            if (i < NN) { g_off[i] = run; g_cur[i] = run; }
            run += v[u];
        }
        __syncthreads();
        if (tid == 0) s_carry = carry + wsum[31];
        __syncthreads();
    }
    if (tid == 0) g_off[NN] = s_carry;
}

// ---------------- fused prep: scatter | encode(+LN0) | wc --------------------
#define SCAT_BLKS 6250
#define ENC_BLKS  1184
__global__ void k_prep(const int* __restrict__ src, const int* __restrict__ dst,
                       const float4* __restrict__ ea,
                       const float* __restrict__ x, const int* __restrict__ nidx,
                       const float* __restrict__ nodef,
                       const float* __restrict__ Woh, const float* __restrict__ boh,
                       const float* __restrict__ Wne, const float* __restrict__ bne,
                       const float* __restrict__ ln0g, const float* __restrict__ ln0b,
                       const float* __restrict__ Wee, const float* __restrict__ bee,
                       const float* __restrict__ We, const float* __restrict__ be) {
    __shared__ float s_woh[64], s_boh[8], s_wne[2048], s_bne[128];
    int b = blockIdx.x;
    if (b < SCAT_BLKS) {
        int i = b * 256 + threadIdx.x;
        if (i < EE) {
            int d = dst[i];
            int pos = atomicAdd(&g_cur[d], 1);
            g_srcp[pos] = src[i];
            float4* o = (float4*)g_eap;
            o[pos * 2]     = ea[i * 2];
            o[pos * 2 + 1] = ea[i * 2 + 1];
        }
        return;
    }
    if (b >= SCAT_BLKS + ENC_BLKS) {
        // ---- fold Wc = Wee @ We, bc = bee@We + be (warp per output) ----
        int lane = threadIdx.x & 31;
        int w = threadIdx.x >> 5;  // 8 warps, loop over outputs
        for (int idx = w; idx < 2304; idx += 8) {
            if (idx < 2048) {
                int bb = idx >> 9, k = (idx >> 6) & 7, c = idx & 63;
                float s = 0.f;
                for (int j = lane; j < 128; j += 32)
                    s += Wee[k * 128 + j] * We[(bb * 128 + j) * 64 + c];
                #pragma unroll
                for (int d = 16; d > 0; d >>= 1) s += __shfl_xor_sync(0xffffffffu, s, d);
                if (lane == 0) g_wc[idx] = s;
            } else {
                int i2 = idx - 2048;
                int bb = i2 >> 6, c = i2 & 63;
                float s = 0.f;
                for (int j = lane; j < 128; j += 32)
                    s += bee[j] * We[(bb * 128 + j) * 64 + c];
                #pragma unroll
                for (int d = 16; d > 0; d >>= 1) s += __shfl_xor_sync(0xffffffffu, s, d);
                if (lane == 0) g_bc[i2] = be[i2] + s;
            }
        }
        return;
    }
    // ---- node encoder + fused LN/relu for block 0 -> bufA ----
    int bb = b - SCAT_BLKS;
    for (int i = threadIdx.x; i < 64; i += 256) s_woh[i] = Woh[i];
    for (int i = threadIdx.x; i < 8; i += 256) s_boh[i] = boh[i];
    for (int i = threadIdx.x; i < 2048; i += 256) s_wne[i] = Wne[i];
    for (int i = threadIdx.x; i < 128; i += 256) s_bne[i] = bne[i];
    __syncthreads();
    int lane = threadIdx.x & 31;
    int warp = bb * 8 + (threadIdx.x >> 5);
    int nw = ENC_BLKS * 8;
    for (int n = warp; n < NN; n += nw) {
        int s = nidx[n];
        float4 a  = *(const float4*)(nodef + s * 8);
        float4 b4 = *(const float4*)(nodef + s * 8 + 4);
        float nf1[8] = {a.x, a.y, a.z, a.w, b4.x, b4.y, b4.z, b4.w};
        float4 xa = *(const float4*)(x + n * 8);
        float4 xb = *(const float4*)(x + n * 8 + 4);
        float xv[8] = {xa.x, xa.y, xa.z, xa.w, xb.x, xb.y, xb.z, xb.w};
        float nf2[8];
        #pragma unroll
        for (int j = 0; j < 8; j++) {
            float t = s_boh[j];
            #pragma unroll
            for (int i = 0; i < 8; i++) t += xv[i] * s_woh[i * 8 + j];
            nf2[j] = t;
        }
        float acc[4];
        #pragma unroll
        for (int cc = 0; cc < 4; cc++) {
            int c = lane + cc * 32;
            float t = s_bne[c];
            #pragma unroll
            for (int k = 0; k < 8; k++) t += nf1[k] * s_wne[k * 128 + c];
            #pragma unroll
            for (int k = 0; k < 8; k++) t += nf2[k] * s_wne[(8 + k) * 128 + c];
            g_h[n * 128 + c] = t;
            acc[cc] = t;
        }
        float v0 = acc[2], v1 = acc[3];
        float su = v0 + v1, q = v0 * v0 + v1 * v1;
        #pragma unroll
        for (int d = 16; d > 0; d >>= 1) {
            su += __shfl_xor_sync(0xffffffffu, su, d);
            q  += __shfl_xor_sync(0xffffffffu, q, d);
        }
        float mu = su * (1.f / 64.f);
        float rs = rsqrtf(q * (1.f / 64.f) - mu * mu + 1e-5f);
        float r0 = fmaxf((v0 - mu) * rs * ln0g[lane] + ln0b[lane], 0.f);
        float r1 = fmaxf((v1 - mu) * rs * ln0g[lane + 32] + ln0b[lane + 32], 0.f);
        g_hblkA[n * 32 + lane] = make_float2(r0, r1);
    }
}

// ----- fused GEN block: warp per node, batch-4 load pipeline ----------------
// agg (unshifted softmax, exact algebra) + MLP + residual + next-block LN.
// All 4 edges' loads issued before any consumption -> >=4 gathers in flight.
__global__ void __launch_bounds__(256) k_aggmlp(
        int bsel, int rdsel, int outoff,
        const float* __restrict__ Wm, const float* __restrict__ bm,
        const float* __restrict__ ng, const float* __restrict__ nb) {
    __shared__ float wms[4096];
    for (int i = threadIdx.x; i < 4096; i += 256) wms[i] = Wm[bsel * 4096 + i];
    __syncthreads();
    const float2* __restrict__ hin = rdsel ? g_hblkB : g_hblkA;
    float2* __restrict__ hout = rdsel ? g_hblkA : g_hblkB;
    int lane = threadIdx.x & 31;
    int node = blockIdx.x * 8 + (threadIdx.x >> 5);   // 12500*8 == NN exactly
    const float* Wc = g_wc + bsel * 512;
    float wA[8], wB[8];
    #pragma unroll
    for (int k = 0; k < 8; k++) {
        wA[k] = __ldg(&Wc[k * 64 + lane]);
        wB[k] = __ldg(&Wc[k * 64 + lane + 32]);
    }
    float bc0 = __ldg(&g_bc[bsel * 64 + lane]);
    float bc1 = __ldg(&g_bc[bsel * 64 + lane + 32]);
    int e0 = __ldg(&g_off[node]), e1 = __ldg(&g_off[node + 1]);
    float d0 = 0.f, d1 = 0.f, n0 = 0.f, n1 = 0.f;
    const float4* eap = (const float4*)g_eap;
    for (int base = e0; base < e1; base += 4) {
        int cnt = min(4, e1 - base);          // warp-uniform
        float2 hv[4];
        float4 Av[4], Bv[4];
        // ---- load phase: all loads issued before any consumption ----
        #pragma unroll
        for (int u = 0; u < 4; u++) {
            if (u < cnt) {
                int s = __ldg(&g_srcp[base + u]);
                hv[u] = __ldg(&hin[s * 32 + lane]);
                Av[u] = __ldg(&eap[(base + u) * 2]);
                Bv[u] = __ldg(&eap[(base + u) * 2 + 1]);
            }
        }
        // ---- compute phase ----
        #pragma unroll
        for (int u = 0; u < 4; u++) {
            if (u < cnt) {
                float t0 = bc0 + hv[u].x, t1 = bc1 + hv[u].y;
                t0 = fmaf(Av[u].x, wA[0], t0);  t1 = fmaf(Av[u].x, wB[0], t1);
                t0 = fmaf(Av[u].y, wA[1], t0);  t1 = fmaf(Av[u].y, wB[1], t1);
                t0 = fmaf(Av[u].z, wA[2], t0);  t1 = fmaf(Av[u].z, wB[2], t1);
                t0 = fmaf(Av[u].w, wA[3], t0);  t1 = fmaf(Av[u].w, wB[3], t1);
                t0 = fmaf(Bv[u].x, wA[4], t0);  t1 = fmaf(Bv[u].x, wB[4], t1);
                t0 = fmaf(Bv[u].y, wA[5], t0);  t1 = fmaf(Bv[u].y, wB[5], t1);
                t0 = fmaf(Bv[u].z, wA[6], t0);  t1 = fmaf(Bv[u].z, wB[6], t1);
                t0 = fmaf(Bv[u].w, wA[7], t0);  t1 = fmaf(Bv[u].w, wB[7], t1);
                float v0 = fmaxf(t0, 0.f);
                float v1 = fmaxf(t1, 0.f);
                float ex0 = __expf(v0);
                float ex1 = __expf(v1);
                d0 += ex0;  n0 = fmaf(v0, ex0, n0);
                d1 += ex1;  n1 = fmaf(v1, ex1, n1);
            }
        }
    }
    float2 hme = __ldg(&hin[node * 32 + lane]);
    float a0 = hme.x + ((e1 > e0) ? (n0 / d0 + 1e-7f) : 0.f);
    float a1 = hme.y + ((e1 > e0) ? (n1 / d1 + 1e-7f) : 0.f);
    // MLP: y = a @ Wm + bm (64x64 warp shfl-GEMM)
    float acc0 = __ldg(&bm[bsel * 64 + lane]);
    float acc1 = __ldg(&bm[bsel * 64 + lane + 32]);
    #pragma unroll
    for (int k = 0; k < 32; k++) {
        float v = __shfl_sync(0xffffffffu, a0, k);
        acc0 = fmaf(v, wms[k * 64 + lane], acc0);
        acc1 = fmaf(v, wms[k * 64 + lane + 32], acc1);
    }
    #pragma unroll
    for (int k = 0; k < 32; k++) {
        float v = __shfl_sync(0xffffffffu, a1, k);
        acc0 = fmaf(v, wms[(k + 32) * 64 + lane], acc0);
        acc1 = fmaf(v, wms[(k + 32) * 64 + lane + 32], acc1);
    }
    float* o = g_h + node * 128 + outoff;
    float y0 = o[lane] + acc0, y1 = o[lane + 32] + acc1;
    o[lane] = y0;  o[lane + 32] = y1;
    if (ng) {
        float su = y0 + y1, q = y0 * y0 + y1 * y1;
        #pragma unroll
        for (int d = 16; d > 0; d >>= 1) {
            su += __shfl_xor_sync(0xffffffffu, su, d);
            q  += __shfl_xor_sync(0xffffffffu, q, d);
        }
        float mu = su * (1.f / 64.f);
        float rs = rsqrtf(q * (1.f / 64.f) - mu * mu + 1e-5f);
        float r0 = fmaxf((y0 - mu) * rs * __ldg(&ng[lane]) + __ldg(&nb[lane]), 0.f);
        float r1 = fmaxf((y1 - mu) * rs * __ldg(&ng[lane + 32]) + __ldg(&nb[lane + 32]), 0.f);
        hout[node * 32 + lane] = make_float2(r0, r1);
    }
}

// ---------------- final: out = relu(LN(h)) @ Wp + bp (56-col chunks) --------
__global__ void k_final(const float* __restrict__ lg, const float* __restrict__ lb,
                        const float* __restrict__ Wp, const float* __restrict__ bp,
                        float* __restrict__ out, int col0) {
    __shared__ float wps[128 * 56];
    for (int i = threadIdx.x; i < 128 * 56; i += blockDim.x) {
        int k = i / 56, c = i % 56;
        wps[i] = Wp[k * 112 + col0 + c];
    }
    __syncthreads();
    int lane = threadIdx.x & 31;
    int warp = blockIdx.x * (blockDim.x >> 5) + (threadIdx.x >> 5);
    int nw = gridDim.x * (blockDim.x >> 5);
    bool hasB = lane < 24;
    int cA = lane, cB = hasB ? lane + 32 : 0;
    float bpA = bp[col0 + cA];
    float bpB = hasB ? bp[col0 + lane + 32] : 0.f;
    float lgv[4], lbv[4];
    #pragma unroll
    for (int i = 0; i < 4; i++) { lgv[i] = lg[lane + i * 32]; lbv[i] = lb[lane + i * 32]; }
    for (int n = warp * 2; n < NN; n += nw * 2) {
        int n2 = n + 1;
        const float* hA = g_h + n * 128;
        const float* hB = g_h + n2 * 128;
        float xA[4], xB[4];
        #pragma unroll
        for (int i = 0; i < 4; i++) { xA[i] = hA[lane + i * 32]; xB[i] = hB[lane + i * 32]; }
        float sA = 0.f, qA = 0.f, sB = 0.f, qB = 0.f;
        #pragma unroll
        for (int i = 0; i < 4; i++) {
            sA += xA[i]; qA += xA[i] * xA[i];
            sB += xB[i]; qB += xB[i] * xB[i];
        }
        #pragma unroll
        for (int d = 16; d > 0; d >>= 1) {
            sA += __shfl_xor_sync(0xffffffffu, sA, d);
            qA += __shfl_xor_sync(0xffffffffu, qA, d);
            sB += __shfl_xor_sync(0xffffffffu, sB, d);
            qB += __shfl_xor_sync(0xffffffffu, qB, d);
        }
        float muA = sA * (1.f / 128.f), muB = sB * (1.f / 128.f);
        float rsA = rsqrtf(qA * (1.f / 128.f) - muA * muA + 1e-5f);
        float rsB = rsqrtf(qB * (1.f / 128.f) - muB * muB + 1e-5f);
        #pragma unroll
        for (int i = 0; i < 4; i++) {
            xA[i] = fmaxf((xA[i] - muA) * rsA * lgv[i] + lbv[i], 0.f);
            xB[i] = fmaxf((xB[i] - muB) * rsB * lgv[i] + lbv[i], 0.f);
        }
        float aA0 = bpA, aA1 = bpB, aB0 = bpA, aB1 = bpB;
        #pragma unroll
        for (int i = 0; i < 4; i++) {
            #pragma unroll
            for (int k = 0; k < 32; k++) {
                float w0 = wps[(k + i * 32) * 56 + cA];
                float w1 = wps[(k + i * 32) * 56 + cB];
                float vA = __shfl_sync(0xffffffffu, xA[i], k);
                float vB = __shfl_sync(0xffffffffu, xB[i], k);
                aA0 = fmaf(vA, w0, aA0);  aA1 = fmaf(vA, w1, aA1);
                aB0 = fmaf(vB, w0, aB0);  aB1 = fmaf(vB, w1, aB1);
            }
        }
        out[n * 112 + col0 + cA] = aA0;
        out[n2 * 112 + col0 + cA] = aB0;
        if (hasB) {
            out[n * 112 + col0 + lane + 32] = aA1;
            out[n2 * 112 + col0 + lane + 32] = aB1;
        }
    }
}

// ---------------- launch ----------------------------------------------------
extern "C" void kernel_launch(void* const* d_in, const int* in_sizes, int n_in,
                              void* d_out, int out_size) {
    const float* x     = (const float*)d_in[0];
    const int*   nidx  = (const int*)d_in[1];
    const int*   ei    = (const int*)d_in[2];
    const float* ea    = (const float*)d_in[3];
    const float* nodef = (const float*)d_in[4];
    const float* Woh   = (const float*)d_in[5];
    const float* boh   = (const float*)d_in[6];
    const float* Wne   = (const float*)d_in[7];
    const float* bne   = (const float*)d_in[8];
    const float* Wee   = (const float*)d_in[9];
    const float* bee   = (const float*)d_in[10];
    const float* lng   = (const float*)d_in[11];
    const float* lnb   = (const float*)d_in[12];
    const float* We    = (const float*)d_in[13];
    const float* be    = (const float*)d_in[14];
    const float* Wm    = (const float*)d_in[15];
    const float* bm    = (const float*)d_in[16];
    const float* lastg = (const float*)d_in[17];
    const float* lastb = (const float*)d_in[18];
    const float* Wp    = (const float*)d_in[19];
    const float* bp    = (const float*)d_in[20];
    float* out = (float*)d_out;

    const int* src = ei;
    const int* dst = ei + EE;

    k_hist<<<(EE + 255) / 256, 256>>>(dst);
    k_scan<<<1, 1024>>>();
    k_prep<<<SCAT_BLKS + ENC_BLKS + 1, 256>>>(src, dst, (const float4*)ea,
                                              x, nidx, nodef, Woh, boh, Wne, bne,
                                              lng, lnb, Wee, bee, We, be);

    for (int b = 0; b < 4; b++) {
        int outoff = (b & 1) ? 64 : 0;
        const float* ng = (b < 3) ? (lng + (b + 1) * 64) : (const float*)0;
        const float* nbp = (b < 3) ? (lnb + (b + 1) * 64) : (const float*)0;
        k_aggmlp<<<NN / 8, 256>>>(b, b & 1, outoff, Wm, bm, ng, nbp);
    }

    k_final<<<1184, 256>>>(lastg, lastb, Wp, bp, out, 0);
    k_final<<<1184, 256>>>(lastg, lastb, Wp, bp, out, 56);
}

// round 9
// speedup vs baseline: 1.4711x; 1.4711x over previous
#include <cuda_runtime.h>

#define NN 100000
#define EE 1600000
#define CAP 384          // staged edges per block (8 nodes, mean 128, P(>384)~1e-9)
#define ENC_BLKS 1184
#define WC_BLKS 32

// ---------------- scratch (static device globals; no allocation) ------------
__device__ float  g_h[NN * 128];       // node features, updated in place
__device__ float2 g_hblkA[NN * 32];    // ping-pong relu(LN(half)) buffers
__device__ float2 g_hblkB[NN * 32];
__device__ int    g_cnt[NN];           // zero-init; re-zeroed by scan each run
__device__ int    g_off[NN + 1];
__device__ int    g_cur[NN];
__device__ int    g_srcp[EE];          // src permuted by dst
__device__ float  g_eap[EE * 8];       // edge_attr permuted by dst
__device__ float  g_wc[4 * 8 * 64];    // folded W_ee @ We per block
__device__ float  g_bc[4 * 64];        // folded bias per block

// ---------------- histogram (lean, standalone) -------------------------------
__global__ void k_hist(const int* __restrict__ dst) {
    int i = blockIdx.x * blockDim.x + threadIdx.x;
    if (i < EE) atomicAdd(&g_cnt[dst[i]], 1);
}

// ------- fused: scan (block 0) | encode+LN0 (blocks 1..1184) | wc (last 32) --
__global__ void k_scan_enc_wc(
        const float* __restrict__ x, const int* __restrict__ nidx,
        const float* __restrict__ nodef,
        const float* __restrict__ Woh, const float* __restrict__ boh,
        const float* __restrict__ Wne, const float* __restrict__ bne,
        const float* __restrict__ ln0g, const float* __restrict__ ln0b,
        const float* __restrict__ Wee, const float* __restrict__ bee,
        const float* __restrict__ We, const float* __restrict__ be) {
    __shared__ float s_woh[64], s_boh[8], s_wne[2048], s_bne[128];
    __shared__ int wsum[8];
    __shared__ int s_carry;
    int tid = threadIdx.x;
    int lane = tid & 31, wid = tid >> 5;
    int b = blockIdx.x;

    if (b == 0) {
        // ---- exclusive scan of g_cnt -> g_off/g_cur; re-zero g_cnt ----
        if (tid == 0) s_carry = 0;
        __syncthreads();
        for (int base = 0; base < NN; base += 4096) {
            int i0 = base + tid * 16;
            int v[16];
            int ts = 0;
            #pragma unroll
            for (int u = 0; u < 16; u++) {
                int i = i0 + u;
                v[u] = (i < NN) ? g_cnt[i] : 0;
                if (i < NN) g_cnt[i] = 0;
                ts += v[u];
            }
            int xv = ts;
            #pragma unroll
            for (int d = 1; d < 32; d <<= 1) {
                int t = __shfl_up_sync(0xffffffffu, xv, d);
                if (lane >= d) xv += t;
            }
            if (lane == 31) wsum[wid] = xv;
            __syncthreads();
            if (wid == 0) {
                int w = (lane < 8) ? wsum[lane] : 0;
                #pragma unroll
                for (int d = 1; d < 8; d <<= 1) {
                    int t = __shfl_up_sync(0xffffffffu, w, d);
                    if (lane >= d) w += t;
                }
                if (lane < 8) wsum[lane] = w;
            }
            __syncthreads();
            int carry = s_carry;
            int run = xv - ts + ((wid > 0) ? wsum[wid - 1] : 0) + carry;
            #pragma unroll
            for (int u = 0; u < 16; u++) {
                int i = i0 + u;
                if (i < NN) { g_off[i] = run; g_cur[i] = run; }
                run += v[u];
            }
            __syncthreads();
            if (tid == 0) s_carry = carry + wsum[7];
            __syncthreads();
        }
        if (tid == 0) g_off[NN] = s_carry;
        return;
    }
    if (b > ENC_BLKS) {
        // ---- fold Wc = Wee@We, bc = bee@We + be (warp per output) ----
        int wcw = (b - ENC_BLKS - 1) * 8 + wid;
        for (int idx = wcw; idx < 2304; idx += WC_BLKS * 8) {
            if (idx < 2048) {
                int bb = idx >> 9, k = (idx >> 6) & 7, c = idx & 63;
                float s = 0.f;
                for (int j = lane; j < 128; j += 32)
                    s += Wee[k * 128 + j] * We[(bb * 128 + j) * 64 + c];
                #pragma unroll
                for (int d = 16; d > 0; d >>= 1) s += __shfl_xor_sync(0xffffffffu, s, d);
                if (lane == 0) g_wc[idx] = s;
            } else {
                int i2 = idx - 2048;
                int bb = i2 >> 6, c = i2 & 63;
                float s = 0.f;
                for (int j = lane; j < 128; j += 32)
                    s += bee[j] * We[(bb * 128 + j) * 64 + c];
                #pragma unroll
                for (int d = 16; d > 0; d >>= 1) s += __shfl_xor_sync(0xffffffffu, s, d);
                if (lane == 0) g_bc[i2] = be[i2] + s;
            }
        }
        return;
    }
    // ---- node encoder + fused LN/relu block 0 -> hblkA ----
    int bb = b - 1;
    for (int i = tid; i < 64; i += 256) s_woh[i] = Woh[i];
    for (int i = tid; i < 8; i += 256) s_boh[i] = boh[i];
    for (int i = tid; i < 2048; i += 256) s_wne[i] = Wne[i];
    for (int i = tid; i < 128; i += 256) s_bne[i] = bne[i];
    __syncthreads();
    int warp = bb * 8 + wid;
    int nw = ENC_BLKS * 8;
    for (int n = warp; n < NN; n += nw) {
        int s = nidx[n];
        float4 a  = *(const float4*)(nodef + s * 8);
        float4 b4 = *(const float4*)(nodef + s * 8 + 4);
        float nf1[8] = {a.x, a.y, a.z, a.w, b4.x, b4.y, b4.z, b4.w};
        float4 xa = *(const float4*)(x + n * 8);
        float4 xb = *(const float4*)(x + n * 8 + 4);
        float xv[8] = {xa.x, xa.y, xa.z, xa.w, xb.x, xb.y, xb.z, xb.w};
        float nf2[8];
        #pragma unroll
        for (int j = 0; j < 8; j++) {
            float t = s_boh[j];
            #pragma unroll
            for (int i = 0; i < 8; i++) t += xv[i] * s_woh[i * 8 + j];
            nf2[j] = t;
        }
        float acc[4];
        #pragma unroll
        for (int cc = 0; cc < 4; cc++) {
            int c = lane + cc * 32;
            float t = s_bne[c];
            #pragma unroll
            for (int k = 0; k < 8; k++) t += nf1[k] * s_wne[k * 128 + c];
            #pragma unroll
            for (int k = 0; k < 8; k++) t += nf2[k] * s_wne[(8 + k) * 128 + c];
            g_h[n * 128 + c] = t;
            acc[cc] = t;
        }
        float v0 = acc[2], v1 = acc[3];
        float su = v0 + v1, q = v0 * v0 + v1 * v1;
        #pragma unroll
        for (int d = 16; d > 0; d >>= 1) {
            su += __shfl_xor_sync(0xffffffffu, su, d);
            q  += __shfl_xor_sync(0xffffffffu, q, d);
        }
        float mu = su * (1.f / 64.f);
        float rs = rsqrtf(q * (1.f / 64.f) - mu * mu + 1e-5f);
        float r0 = fmaxf((v0 - mu) * rs * ln0g[lane] + ln0b[lane], 0.f);
        float r1 = fmaxf((v1 - mu) * rs * ln0g[lane + 32] + ln0b[lane + 32], 0.f);
        g_hblkA[n * 32 + lane] = make_float2(r0, r1);
    }
}

// ---------------- scatter edges by dst (lean, standalone) --------------------
__global__ void k_scatter(const int* __restrict__ src, const int* __restrict__ dst,
                          const float4* __restrict__ ea) {
    int i = blockIdx.x * blockDim.x + threadIdx.x;
    if (i < EE) {
        int d = dst[i];
        int pos = atomicAdd(&g_cur[d], 1);
        g_srcp[pos] = src[i];
        float4* o = (float4*)g_eap;
        o[pos * 2]     = ea[i * 2];
        o[pos * 2 + 1] = ea[i * 2 + 1];
    }
}

// ----- fused GEN block: smem-staged edges + pipelined gather + MLP + LN ------
// Block owns 8 consecutive nodes = ONE contiguous edge range (sorted by dst).
// Stage srcp+eap in smem (coalesced); per edge only ONE global load remains
// (the random hblk gather), software-pipelined depth 2.
// Unshifted softmax (exact: msg bounded; weights invariant to shift/+eps;
// agg = sum(relu*w) + eps, guarded so empty nodes stay exactly 0).
__global__ void __launch_bounds__(256, 4) k_aggmlp(
        int bsel, int rdsel, int outoff,
        const float* __restrict__ Wm, const float* __restrict__ bm,
        const float* __restrict__ ng, const float* __restrict__ nb) {
    __shared__ float wms[4096];
    __shared__ float4 s_eap[CAP * 2];
    __shared__ int s_src[CAP];
    int tid = threadIdx.x;
    int lane = tid & 31, wid = tid >> 5;
    for (int i = tid; i < 4096; i += 256) wms[i] = Wm[bsel * 4096 + i];
    int node0 = blockIdx.x * 8;                 // 12500*8 == NN exactly
    int b0 = __ldg(&g_off[node0]);
    int bend = __ldg(&g_off[node0 + 8]);
    int staged = min(bend - b0, CAP);
    const float4* eap = (const float4*)g_eap;
    for (int j = tid; j < staged * 2; j += 256) s_eap[j] = __ldg(&eap[b0 * 2 + j]);
    for (int j = tid; j < staged; j += 256) s_src[j] = __ldg(&g_srcp[b0 + j]);
    __syncthreads();

    const float2* __restrict__ hin = rdsel ? g_hblkB : g_hblkA;
    float2* __restrict__ hout = rdsel ? g_hblkA : g_hblkB;
    int node = node0 + wid;
    const float* Wc = g_wc + bsel * 512;
    float wA[8], wB[8];
    #pragma unroll
    for (int k = 0; k < 8; k++) {
        wA[k] = __ldg(&Wc[k * 64 + lane]);
        wB[k] = __ldg(&Wc[k * 64 + lane + 32]);
    }
    float bc0 = __ldg(&g_bc[bsel * 64 + lane]);
    float bc1 = __ldg(&g_bc[bsel * 64 + lane + 32]);
    int e0 = __ldg(&g_off[node]), e1 = __ldg(&g_off[node + 1]);
    int l0 = e0 - b0, l1 = e1 - b0;
    int lim1 = min(l1, staged);
    float d0 = 0.f, d1 = 0.f, n0 = 0.f, n1 = 0.f;

    #define CONSUME_SMEM(l, hv)                                              \
    {                                                                        \
        float4 A = s_eap[(l) * 2];                                           \
        float4 B = s_eap[(l) * 2 + 1];                                       \
        float t0 = bc0 + (hv).x, t1 = bc1 + (hv).y;                          \
        t0 = fmaf(A.x, wA[0], t0);  t1 = fmaf(A.x, wB[0], t1);               \
        t0 = fmaf(A.y, wA[1], t0);  t1 = fmaf(A.y, wB[1], t1);               \
        t0 = fmaf(A.z, wA[2], t0);  t1 = fmaf(A.z, wB[2], t1);               \
        t0 = fmaf(A.w, wA[3], t0);  t1 = fmaf(A.w, wB[3], t1);               \
        t0 = fmaf(B.x, wA[4], t0);  t1 = fmaf(B.x, wB[4], t1);               \
        t0 = fmaf(B.y, wA[5], t0);  t1 = fmaf(B.y, wB[5], t1);               \
        t0 = fmaf(B.z, wA[6], t0);  t1 = fmaf(B.z, wB[6], t1);               \
        t0 = fmaf(B.w, wA[7], t0);  t1 = fmaf(B.w, wB[7], t1);               \
        float v0 = fmaxf(t0, 0.f);                                           \
        float v1 = fmaxf(t1, 0.f);                                           \
        float ex0 = __expf(v0);                                              \
        float ex1 = __expf(v1);                                              \
        d0 += ex0;  n0 = fmaf(v0, ex0, n0);                                  \
        d1 += ex1;  n1 = fmaf(v1, ex1, n1);                                  \
    }

    int l = l0;
    if (l < lim1) {
        // depth-2 pipeline on the single remaining global load (hblk gather)
        int s0 = s_src[l];
        float2 h0 = __ldg(&hin[s0 * 32 + lane]);
        for (; l + 1 < lim1; l++) {
            int s1 = s_src[l + 1];
            float2 h1 = __ldg(&hin[s1 * 32 + lane]);
            CONSUME_SMEM(l, h0);
            h0 = h1;
        }
        CONSUME_SMEM(l, h0);
        l++;
    }
    // overflow tail (rare): all-global path
    for (l = max(l0, lim1); l < l1; l++) {
        int s = __ldg(&g_srcp[b0 + l]);
        float2 hv = __ldg(&hin[s * 32 + lane]);
        float4 A = __ldg(&eap[(b0 + l) * 2]);
        float4 B = __ldg(&eap[(b0 + l) * 2 + 1]);
        float t0 = bc0 + hv.x, t1 = bc1 + hv.y;
        t0 = fmaf(A.x, wA[0], t0);  t1 = fmaf(A.x, wB[0], t1);
        t0 = fmaf(A.y, wA[1], t0);  t1 = fmaf(A.y, wB[1], t1);
        t0 = fmaf(A.z, wA[2], t0);  t1 = fmaf(A.z, wB[2], t1);
        t0 = fmaf(A.w, wA[3], t0);  t1 = fmaf(A.w, wB[3], t1);
        t0 = fmaf(B.x, wA[4], t0);  t1 = fmaf(B.x, wB[4], t1);
        t0 = fmaf(B.y, wA[5], t0);  t1 = fmaf(B.y, wB[5], t1);
        t0 = fmaf(B.z, wA[6], t0);  t1 = fmaf(B.z, wB[6], t1);
        t0 = fmaf(B.w, wA[7], t0);  t1 = fmaf(B.w, wB[7], t1);
        float v0 = fmaxf(t0, 0.f);
        float v1 = fmaxf(t1, 0.f);
        float ex0 = __expf(v0);
        float ex1 = __expf(v1);
        d0 += ex0;  n0 = fmaf(v0, ex0, n0);
        d1 += ex1;  n1 = fmaf(v1, ex1, n1);
    }

    float2 hme = __ldg(&hin[node * 32 + lane]);
    float a0 = hme.x + ((e1 > e0) ? (n0 / d0 + 1e-7f) : 0.f);
    float a1 = hme.y + ((e1 > e0) ? (n1 / d1 + 1e-7f) : 0.f);
    // MLP: y = a @ Wm + bm (64x64 warp shfl-GEMM)
    float acc0 = __ldg(&bm[bsel * 64 + lane]);
    float acc1 = __ldg(&bm[bsel * 64 + lane + 32]);
    #pragma unroll
    for (int k = 0; k < 32; k++) {
        float v = __shfl_sync(0xffffffffu, a0, k);
        acc0 = fmaf(v, wms[k * 64 + lane], acc0);
        acc1 = fmaf(v, wms[k * 64 + lane + 32], acc1);
    }
    #pragma unroll
    for (int k = 0; k < 32; k++) {
        float v = __shfl_sync(0xffffffffu, a1, k);
        acc0 = fmaf(v, wms[(k + 32) * 64 + lane], acc0);
        acc1 = fmaf(v, wms[(k + 32) * 64 + lane + 32], acc1);
    }
    float* o = g_h + node * 128 + outoff;
    float y0 = o[lane] + acc0, y1 = o[lane + 32] + acc1;
    o[lane] = y0;  o[lane + 32] = y1;
    if (ng) {
        float su = y0 + y1, q = y0 * y0 + y1 * y1;
        #pragma unroll
        for (int d = 16; d > 0; d >>= 1) {
            su += __shfl_xor_sync(0xffffffffu, su, d);
            q  += __shfl_xor_sync(0xffffffffu, q, d);
        }
        float mu = su * (1.f / 64.f);
        float rs = rsqrtf(q * (1.f / 64.f) - mu * mu + 1e-5f);
        float r0 = fmaxf((y0 - mu) * rs * __ldg(&ng[lane]) + __ldg(&nb[lane]), 0.f);
        float r1 = fmaxf((y1 - mu) * rs * __ldg(&ng[lane + 32]) + __ldg(&nb[lane + 32]), 0.f);
        hout[node * 32 + lane] = make_float2(r0, r1);
    }
}

// ---------------- final: out = relu(LN(h)) @ Wp + bp (56-col chunks) --------
__global__ void k_final(const float* __restrict__ lg, const float* __restrict__ lb,
                        const float* __restrict__ Wp, const float* __restrict__ bp,
                        float* __restrict__ out, int col0) {
    __shared__ float wps[128 * 56];
    for (int i = threadIdx.x; i < 128 * 56; i += blockDim.x) {
        int k = i / 56, c = i % 56;
        wps[i] = Wp[k * 112 + col0 + c];
    }
    __syncthreads();
    int lane = threadIdx.x & 31;
    int warp = blockIdx.x * (blockDim.x >> 5) + (threadIdx.x >> 5);
    int nw = gridDim.x * (blockDim.x >> 5);
    bool hasB = lane < 24;
    int cA = lane, cB = hasB ? lane + 32 : 0;
    float bpA = bp[col0 + cA];
    float bpB = hasB ? bp[col0 + lane + 32] : 0.f;
    float lgv[4], lbv[4];
    #pragma unroll
    for (int i = 0; i < 4; i++) { lgv[i] = lg[lane + i * 32]; lbv[i] = lb[lane + i * 32]; }
    for (int n = warp * 2; n < NN; n += nw * 2) {
        int n2 = n + 1;
        const float* hA = g_h + n * 128;
        const float* hB = g_h + n2 * 128;
        float xA[4], xB[4];
        #pragma unroll
        for (int i = 0; i < 4; i++) { xA[i] = hA[lane + i * 32]; xB[i] = hB[lane + i * 32]; }
        float sA = 0.f, qA = 0.f, sB = 0.f, qB = 0.f;
        #pragma unroll
        for (int i = 0; i < 4; i++) {
            sA += xA[i]; qA += xA[i] * xA[i];
            sB += xB[i]; qB += xB[i] * xB[i];
        }
        #pragma unroll
        for (int d = 16; d > 0; d >>= 1) {
            sA += __shfl_xor_sync(0xffffffffu, sA, d);
            qA += __shfl_xor_sync(0xffffffffu, qA, d);
            sB += __shfl_xor_sync(0xffffffffu, sB, d);
            qB += __shfl_xor_sync(0xffffffffu, qB, d);
        }
        float muA = sA * (1.f / 128.f), muB = sB * (1.f / 128.f);
        float rsA = rsqrtf(qA * (1.f / 128.f) - muA * muA + 1e-5f);
        float rsB = rsqrtf(qB * (1.f / 128.f) - muB * muB + 1e-5f);
        #pragma unroll
        for (int i = 0; i < 4; i++) {
            xA[i] = fmaxf((xA[i] - muA) * rsA * lgv[i] + lbv[i], 0.f);
            xB[i] = fmaxf((xB[i] - muB) * rsB * lgv[i] + lbv[i], 0.f);
        }
        float aA0 = bpA, aA1 = bpB, aB0 = bpA, aB1 = bpB;
        #pragma unroll
        for (int i = 0; i < 4; i++) {
            #pragma unroll
            for (int k = 0; k < 32; k++) {
                float w0 = wps[(k + i * 32) * 56 + cA];
                float w1 = wps[(k + i * 32) * 56 + cB];
                float vA = __shfl_sync(0xffffffffu, xA[i], k);
                float vB = __shfl_sync(0xffffffffu, xB[i], k);
                aA0 = fmaf(vA, w0, aA0);  aA1 = fmaf(vA, w1, aA1);
                aB0 = fmaf(vB, w0, aB0);  aB1 = fmaf(vB, w1, aB1);
            }
        }
        out[n * 112 + col0 + cA] = aA0;
        out[n2 * 112 + col0 + cA] = aB0;
        if (hasB) {
            out[n * 112 + col0 + lane + 32] = aA1;
            out[n2 * 112 + col0 + lane + 32] = aB1;
        }
    }
}

// ---------------- launch ----------------------------------------------------
extern "C" void kernel_launch(void* const* d_in, const int* in_sizes, int n_in,
                              void* d_out, int out_size) {
    const float* x     = (const float*)d_in[0];
    const int*   nidx  = (const int*)d_in[1];
    const int*   ei    = (const int*)d_in[2];
    const float* ea    = (const float*)d_in[3];
    const float* nodef = (const float*)d_in[4];
    const float* Woh   = (const float*)d_in[5];
    const float* boh   = (const float*)d_in[6];
    const float* Wne   = (const float*)d_in[7];
    const float* bne   = (const float*)d_in[8];
    const float* Wee   = (const float*)d_in[9];
    const float* bee   = (const float*)d_in[10];
    const float* lng   = (const float*)d_in[11];
    const float* lnb   = (const float*)d_in[12];
    const float* We    = (const float*)d_in[13];
    const float* be    = (const float*)d_in[14];
    const float* Wm    = (const float*)d_in[15];
    const float* bm    = (const float*)d_in[16];
    const float* lastg = (const float*)d_in[17];
    const float* lastb = (const float*)d_in[18];
    const float* Wp    = (const float*)d_in[19];
    const float* bp    = (const float*)d_in[20];
    float* out = (float*)d_out;

    const int* src = ei;
    const int* dst = ei + EE;

    k_hist<<<(EE + 255) / 256, 256>>>(dst);
    k_scan_enc_wc<<<1 + ENC_BLKS + WC_BLKS, 256>>>(x, nidx, nodef, Woh, boh,
                                                   Wne, bne, lng, lnb,
                                                   Wee, bee, We, be);
    k_scatter<<<(EE + 255) / 256, 256>>>(src, dst, (const float4*)ea);

    for (int b = 0; b < 4; b++) {
        int outoff = (b & 1) ? 64 : 0;
        const float* ng = (b < 3) ? (lng + (b + 1) * 64) : (const float*)0;
        const float* nbp = (b < 3) ? (lnb + (b + 1) * 64) : (const float*)0;
        k_aggmlp<<<NN / 8, 256>>>(b, b & 1, outoff, Wm, bm, ng, nbp);
    }

    k_final<<<1184, 256>>>(lastg, lastb, Wp, bp, out, 0);
    k_final<<<1184, 256>>>(lastg, lastb, Wp, bp, out, 56);
}

// round 10
// speedup vs baseline: 1.5565x; 1.0581x over previous
#include <cuda_runtime.h>

#define NN 100000
#define EE 1600000
#define CAP 384          // staged edges per block (8 nodes, mean 128)
#define ENC_BLKS 1184
#define WC_BLKS 32

// ---------------- scratch (static device globals; no allocation) ------------
__device__ float  g_h[NN * 128];       // node features, updated in place
__device__ float2 g_hblkA[NN * 32];    // ping-pong relu(LN(half)) buffers
__device__ float2 g_hblkB[NN * 32];
__device__ int    g_cnt[NN];           // zero-init; re-zeroed by scan each run
__device__ int    g_off[NN + 1];
__device__ int    g_cur[NN];
__device__ int    g_srcp[EE];          // src permuted by dst
__device__ float  g_eap[EE * 8];       // edge_attr permuted by dst
__device__ float  g_wc[4 * 8 * 64];    // folded W_ee @ We per block
__device__ float  g_bc[4 * 64];        // folded bias per block

// ---------------- histogram (lean, standalone) -------------------------------
__global__ void k_hist(const int* __restrict__ dst) {
    int i = blockIdx.x * blockDim.x + threadIdx.x;
    if (i < EE) atomicAdd(&g_cnt[dst[i]], 1);
}

// ------- fused: scan (block 0) | encode+LN0 (blocks 1..1184) | wc (last 32) --
__global__ void k_scan_enc_wc(
        const float* __restrict__ x, const int* __restrict__ nidx,
        const float* __restrict__ nodef,
        const float* __restrict__ Woh, const float* __restrict__ boh,
        const float* __restrict__ Wne, const float* __restrict__ bne,
        const float* __restrict__ ln0g, const float* __restrict__ ln0b,
        const float* __restrict__ Wee, const float* __restrict__ bee,
        const float* __restrict__ We, const float* __restrict__ be) {
    __shared__ float s_woh[64], s_boh[8], s_wne[2048], s_bne[128];
    __shared__ int wsum[8];
    __shared__ int s_carry;
    int tid = threadIdx.x;
    int lane = tid & 31, wid = tid >> 5;
    int b = blockIdx.x;

    if (b == 0) {
        if (tid == 0) s_carry = 0;
        __syncthreads();
        for (int base = 0; base < NN; base += 4096) {
            int i0 = base + tid * 16;
            int v[16];
            int ts = 0;
            #pragma unroll
            for (int u = 0; u < 16; u++) {
                int i = i0 + u;
                v[u] = (i < NN) ? g_cnt[i] : 0;
                if (i < NN) g_cnt[i] = 0;
                ts += v[u];
            }
            int xv = ts;
            #pragma unroll
            for (int d = 1; d < 32; d <<= 1) {
                int t = __shfl_up_sync(0xffffffffu, xv, d);
                if (lane >= d) xv += t;
            }
            if (lane == 31) wsum[wid] = xv;
            __syncthreads();
            if (wid == 0) {
                int w = (lane < 8) ? wsum[lane] : 0;
                #pragma unroll
                for (int d = 1; d < 8; d <<= 1) {
                    int t = __shfl_up_sync(0xffffffffu, w, d);
                    if (lane >= d) w += t;
                }
                if (lane < 8) wsum[lane] = w;
            }
            __syncthreads();
            int carry = s_carry;
            int run = xv - ts + ((wid > 0) ? wsum[wid - 1] : 0) + carry;
            #pragma unroll
            for (int u = 0; u < 16; u++) {
                int i = i0 + u;
                if (i < NN) { g_off[i] = run; g_cur[i] = run; }
                run += v[u];
            }
            __syncthreads();
            if (tid == 0) s_carry = carry + wsum[7];
            __syncthreads();
        }
        if (tid == 0) g_off[NN] = s_carry;
        return;
    }
    if (b > ENC_BLKS) {
        int wcw = (b - ENC_BLKS - 1) * 8 + wid;
        for (int idx = wcw; idx < 2304; idx += WC_BLKS * 8) {
            if (idx < 2048) {
                int bb = idx >> 9, k = (idx >> 6) & 7, c = idx & 63;
                float s = 0.f;
                for (int j = lane; j < 128; j += 32)
                    s += Wee[k * 128 + j] * We[(bb * 128 + j) * 64 + c];
                #pragma unroll
                for (int d = 16; d > 0; d >>= 1) s += __shfl_xor_sync(0xffffffffu, s, d);
                if (lane == 0) g_wc[idx] = s;
            } else {
                int i2 = idx - 2048;
                int bb = i2 >> 6, c = i2 & 63;
                float s = 0.f;
                for (int j = lane; j < 128; j += 32)
                    s += bee[j] * We[(bb * 128 + j) * 64 + c];
                #pragma unroll
                for (int d = 16; d > 0; d >>= 1) s += __shfl_xor_sync(0xffffffffu, s, d);
                if (lane == 0) g_bc[i2] = be[i2] + s;
            }
        }
        return;
    }
    // ---- node encoder + fused LN/relu block 0 -> hblkA ----
    int bb = b - 1;
    for (int i = tid; i < 64; i += 256) s_woh[i] = Woh[i];
    for (int i = tid; i < 8; i += 256) s_boh[i] = boh[i];
    for (int i = tid; i < 2048; i += 256) s_wne[i] = Wne[i];
    for (int i = tid; i < 128; i += 256) s_bne[i] = bne[i];
    __syncthreads();
    int warp = bb * 8 + wid;
    int nw = ENC_BLKS * 8;
    for (int n = warp; n < NN; n += nw) {
        int s = nidx[n];
        float4 a  = *(const float4*)(nodef + s * 8);
        float4 b4 = *(const float4*)(nodef + s * 8 + 4);
        float nf1[8] = {a.x, a.y, a.z, a.w, b4.x, b4.y, b4.z, b4.w};
        float4 xa = *(const float4*)(x + n * 8);
        float4 xb = *(const float4*)(x + n * 8 + 4);
        float xv[8] = {xa.x, xa.y, xa.z, xa.w, xb.x, xb.y, xb.z, xb.w};
        float nf2[8];
        #pragma unroll
        for (int j = 0; j < 8; j++) {
            float t = s_boh[j];
            #pragma unroll
            for (int i = 0; i < 8; i++) t += xv[i] * s_woh[i * 8 + j];
            nf2[j] = t;
        }
        float acc[4];
        #pragma unroll
        for (int cc = 0; cc < 4; cc++) {
            int c = lane + cc * 32;
            float t = s_bne[c];
            #pragma unroll
            for (int k = 0; k < 8; k++) t += nf1[k] * s_wne[k * 128 + c];
            #pragma unroll
            for (int k = 0; k < 8; k++) t += nf2[k] * s_wne[(8 + k) * 128 + c];
            g_h[n * 128 + c] = t;
            acc[cc] = t;
        }
        float v0 = acc[2], v1 = acc[3];
        float su = v0 + v1, q = v0 * v0 + v1 * v1;
        #pragma unroll
        for (int d = 16; d > 0; d >>= 1) {
            su += __shfl_xor_sync(0xffffffffu, su, d);
            q  += __shfl_xor_sync(0xffffffffu, q, d);
        }
        float mu = su * (1.f / 64.f);
        float rs = rsqrtf(q * (1.f / 64.f) - mu * mu + 1e-5f);
        float r0 = fmaxf((v0 - mu) * rs * ln0g[lane] + ln0b[lane], 0.f);
        float r1 = fmaxf((v1 - mu) * rs * ln0g[lane + 32] + ln0b[lane + 32], 0.f);
        g_hblkA[n * 32 + lane] = make_float2(r0, r1);
    }
}

// ---------------- scatter edges by dst (lean, standalone) --------------------
__global__ void k_scatter(const int* __restrict__ src, const int* __restrict__ dst,
                          const float4* __restrict__ ea) {
    int i = blockIdx.x * blockDim.x + threadIdx.x;
    if (i < EE) {
        int d = dst[i];
        int pos = atomicAdd(&g_cur[d], 1);
        g_srcp[pos] = src[i];
        float4* o = (float4*)g_eap;
        o[pos * 2]     = ea[i * 2];
        o[pos * 2 + 1] = ea[i * 2 + 1];
    }
}

// ----- fused GEN block: smem-staged edges + depth-3 gather pipeline ---------
// + MLP with paired-weight float2 LDS + residual + next-block LN (ping-pong).
// Unshifted softmax (exact: msg bounded; weights invariant to shift/+eps;
// agg = sum(relu*w) + eps, guarded so empty nodes stay exactly 0).
__global__ void __launch_bounds__(256, 4) k_aggmlp(
        int bsel, int rdsel, int outoff,
        const float* __restrict__ Wm, const float* __restrict__ bm,
        const float* __restrict__ ng, const float* __restrict__ nb) {
    __shared__ float wms[4096];          // paired layout: (w[k][c], w[k][c+32])
    __shared__ float4 s_eap[CAP * 2];
    __shared__ int s_src[CAP];
    int tid = threadIdx.x;
    int lane = tid & 31, wid = tid >> 5;
    // paired staging: wms[k*64 + 2c+h] = Wm[k*64 + c + h*32]
    for (int i = tid; i < 4096; i += 256) {
        int k = i >> 6, c = i & 63;
        int col = (c >> 1) + ((c & 1) << 5);
        wms[i] = Wm[bsel * 4096 + k * 64 + col];
    }
    int node0 = blockIdx.x * 8;                 // 12500*8 == NN exactly
    int b0 = __ldg(&g_off[node0]);
    int bend = __ldg(&g_off[node0 + 8]);
    int staged = min(bend - b0, CAP);
    const float4* eap = (const float4*)g_eap;
    for (int j = tid; j < staged * 2; j += 256) s_eap[j] = __ldg(&eap[b0 * 2 + j]);
    for (int j = tid; j < staged; j += 256) s_src[j] = __ldg(&g_srcp[b0 + j]);
    __syncthreads();

    const float2* __restrict__ hin = rdsel ? g_hblkB : g_hblkA;
    float2* __restrict__ hout = rdsel ? g_hblkA : g_hblkB;
    int node = node0 + wid;
    const float* Wc = g_wc + bsel * 512;
    float wA[8], wB[8];
    #pragma unroll
    for (int k = 0; k < 8; k++) {
        wA[k] = __ldg(&Wc[k * 64 + lane]);
        wB[k] = __ldg(&Wc[k * 64 + lane + 32]);
    }
    float bc0 = __ldg(&g_bc[bsel * 64 + lane]);
    float bc1 = __ldg(&g_bc[bsel * 64 + lane + 32]);
    int e0 = __ldg(&g_off[node]), e1 = __ldg(&g_off[node + 1]);
    int l0 = e0 - b0, l1 = e1 - b0;
    int lim1 = min(l1, staged);
    float d0 = 0.f, d1 = 0.f, n0 = 0.f, n1 = 0.f;

    #define CONSUME_SMEM(l, hv)                                              \
    {                                                                        \
        float4 A = s_eap[(l) * 2];                                           \
        float4 B = s_eap[(l) * 2 + 1];                                       \
        float t0 = bc0 + (hv).x, t1 = bc1 + (hv).y;                          \
        t0 = fmaf(A.x, wA[0], t0);  t1 = fmaf(A.x, wB[0], t1);               \
        t0 = fmaf(A.y, wA[1], t0);  t1 = fmaf(A.y, wB[1], t1);               \
        t0 = fmaf(A.z, wA[2], t0);  t1 = fmaf(A.z, wB[2], t1);               \
        t0 = fmaf(A.w, wA[3], t0);  t1 = fmaf(A.w, wB[3], t1);               \
        t0 = fmaf(B.x, wA[4], t0);  t1 = fmaf(B.x, wB[4], t1);               \
        t0 = fmaf(B.y, wA[5], t0);  t1 = fmaf(B.y, wB[5], t1);               \
        t0 = fmaf(B.z, wA[6], t0);  t1 = fmaf(B.z, wB[6], t1);               \
        t0 = fmaf(B.w, wA[7], t0);  t1 = fmaf(B.w, wB[7], t1);               \
        float v0 = fmaxf(t0, 0.f);                                           \
        float v1 = fmaxf(t1, 0.f);                                           \
        float ex0 = __expf(v0);                                              \
        float ex1 = __expf(v1);                                              \
        d0 += ex0;  n0 = fmaf(v0, ex0, n0);                                  \
        d1 += ex1;  n1 = fmaf(v1, ex1, n1);                                  \
    }

    int l = l0;
    int rem = lim1 - l0;
    if (rem > 0) {
        // depth-3 pipeline on the single remaining global load (hblk gather)
        float2 h0 = __ldg(&hin[s_src[l] * 32 + lane]);
        float2 h1 = (rem > 1) ? __ldg(&hin[s_src[l + 1] * 32 + lane]) : h0;
        for (; l + 2 < lim1; l++) {
            float2 h2 = __ldg(&hin[s_src[l + 2] * 32 + lane]);
            CONSUME_SMEM(l, h0);
            h0 = h1;
            h1 = h2;
        }
        if (l < lim1) { CONSUME_SMEM(l, h0); l++; }
        if (l < lim1) { CONSUME_SMEM(l, h1); l++; }
    }
    // overflow tail (rare): all-global path
    for (l = max(l0, lim1); l < l1; l++) {
        int s = __ldg(&g_srcp[b0 + l]);
        float2 hv = __ldg(&hin[s * 32 + lane]);
        float4 A = __ldg(&eap[(b0 + l) * 2]);
        float4 B = __ldg(&eap[(b0 + l) * 2 + 1]);
        float t0 = bc0 + hv.x, t1 = bc1 + hv.y;
        t0 = fmaf(A.x, wA[0], t0);  t1 = fmaf(A.x, wB[0], t1);
        t0 = fmaf(A.y, wA[1], t0);  t1 = fmaf(A.y, wB[1], t1);
        t0 = fmaf(A.z, wA[2], t0);  t1 = fmaf(A.z, wB[2], t1);
        t0 = fmaf(A.w, wA[3], t0);  t1 = fmaf(A.w, wB[3], t1);
        t0 = fmaf(B.x, wA[4], t0);  t1 = fmaf(B.x, wB[4], t1);
        t0 = fmaf(B.y, wA[5], t0);  t1 = fmaf(B.y, wB[5], t1);
        t0 = fmaf(B.z, wA[6], t0);  t1 = fmaf(B.z, wB[6], t1);
        t0 = fmaf(B.w, wA[7], t0);  t1 = fmaf(B.w, wB[7], t1);
        float v0 = fmaxf(t0, 0.f);
        float v1 = fmaxf(t1, 0.f);
        float ex0 = __expf(v0);
        float ex1 = __expf(v1);
        d0 += ex0;  n0 = fmaf(v0, ex0, n0);
        d1 += ex1;  n1 = fmaf(v1, ex1, n1);
    }

    float2 hme = __ldg(&hin[node * 32 + lane]);
    float a0 = hme.x + ((e1 > e0) ? (n0 / d0 + 1e-7f) : 0.f);
    float a1 = hme.y + ((e1 > e0) ? (n1 / d1 + 1e-7f) : 0.f);
    // MLP: y = a @ Wm + bm (64x64 warp shfl-GEMM, paired float2 weight LDS)
    float acc0 = __ldg(&bm[bsel * 64 + lane]);
    float acc1 = __ldg(&bm[bsel * 64 + lane + 32]);
    const float2* wm2 = (const float2*)wms;
    #pragma unroll
    for (int k = 0; k < 32; k++) {
        float2 w = wm2[k * 32 + lane];
        float v = __shfl_sync(0xffffffffu, a0, k);
        acc0 = fmaf(v, w.x, acc0);
        acc1 = fmaf(v, w.y, acc1);
    }
    #pragma unroll
    for (int k = 0; k < 32; k++) {
        float2 w = wm2[(k + 32) * 32 + lane];
        float v = __shfl_sync(0xffffffffu, a1, k);
        acc0 = fmaf(v, w.x, acc0);
        acc1 = fmaf(v, w.y, acc1);
    }
    float* o = g_h + node * 128 + outoff;
    float y0 = o[lane] + acc0, y1 = o[lane + 32] + acc1;
    o[lane] = y0;  o[lane + 32] = y1;
    if (ng) {
        float su = y0 + y1, q = y0 * y0 + y1 * y1;
        #pragma unroll
        for (int d = 16; d > 0; d >>= 1) {
            su += __shfl_xor_sync(0xffffffffu, su, d);
            q  += __shfl_xor_sync(0xffffffffu, q, d);
        }
        float mu = su * (1.f / 64.f);
        float rs = rsqrtf(q * (1.f / 64.f) - mu * mu + 1e-5f);
        float r0 = fmaxf((y0 - mu) * rs * __ldg(&ng[lane]) + __ldg(&nb[lane]), 0.f);
        float r1 = fmaxf((y1 - mu) * rs * __ldg(&ng[lane + 32]) + __ldg(&nb[lane + 32]), 0.f);
        hout[node * 32 + lane] = make_float2(r0, r1);
    }
}

// ---------------- final: out = relu(LN(h)) @ Wp + bp (56-col chunks) --------
// Paired weight layout: wps[k*64 + 2c+h] = Wp[k][col0 + c + h*32] (0-padded).
__global__ void k_final(const float* __restrict__ lg, const float* __restrict__ lb,
                        const float* __restrict__ Wp, const float* __restrict__ bp,
                        float* __restrict__ out, int col0) {
    __shared__ float wps[128 * 64];
    for (int i = threadIdx.x; i < 128 * 64; i += blockDim.x) {
        int k = i >> 6, c = i & 63;
        int col = (c >> 1) + ((c & 1) << 5);
        wps[i] = (col < 56) ? Wp[k * 112 + col0 + col] : 0.f;
    }
    __syncthreads();
    int lane = threadIdx.x & 31;
    int warp = blockIdx.x * (blockDim.x >> 5) + (threadIdx.x >> 5);
    int nw = gridDim.x * (blockDim.x >> 5);
    bool hasB = lane < 24;
    float bpA = bp[col0 + lane];
    float bpB = hasB ? bp[col0 + lane + 32] : 0.f;
    float lgv[4], lbv[4];
    #pragma unroll
    for (int i = 0; i < 4; i++) { lgv[i] = lg[lane + i * 32]; lbv[i] = lb[lane + i * 32]; }
    const float2* wp2 = (const float2*)wps;
    for (int n = warp * 2; n < NN; n += nw * 2) {
        int n2 = n + 1;
        const float* hA = g_h + n * 128;
        const float* hB = g_h + n2 * 128;
        float xA[4], xB[4];
        #pragma unroll
        for (int i = 0; i < 4; i++) { xA[i] = hA[lane + i * 32]; xB[i] = hB[lane + i * 32]; }
        float sA = 0.f, qA = 0.f, sB = 0.f, qB = 0.f;
        #pragma unroll
        for (int i = 0; i < 4; i++) {
            sA += xA[i]; qA += xA[i] * xA[i];
            sB += xB[i]; qB += xB[i] * xB[i];
        }
        #pragma unroll
        for (int d = 16; d > 0; d >>= 1) {
            sA += __shfl_xor_sync(0xffffffffu, sA, d);
            qA += __shfl_xor_sync(0xffffffffu, qA, d);
            sB += __shfl_xor_sync(0xffffffffu, sB, d);
            qB += __shfl_xor_sync(0xffffffffu, qB, d);
        }
        float muA = sA * (1.f / 128.f), muB = sB * (1.f / 128.f);
        float rsA = rsqrtf(qA * (1.f / 128.f) - muA * muA + 1e-5f);
        float rsB = rsqrtf(qB * (1.f / 128.f) - muB * muB + 1e-5f);
        #pragma unroll
        for (int i = 0; i < 4; i++) {
            xA[i] = fmaxf((xA[i] - muA) * rsA * lgv[i] + lbv[i], 0.f);
            xB[i] = fmaxf((xB[i] - muB) * rsB * lgv[i] + lbv[i], 0.f);
        }
        float aA0 = bpA, aA1 = bpB, aB0 = bpA, aB1 = bpB;
        #pragma unroll
        for (int i = 0; i < 4; i++) {
            #pragma unroll
            for (int k = 0; k < 32; k++) {
                float2 w = wp2[(k + i * 32) * 32 + lane];
                float vA = __shfl_sync(0xffffffffu, xA[i], k);
                float vB = __shfl_sync(0xffffffffu, xB[i], k);
                aA0 = fmaf(vA, w.x, aA0);  aA1 = fmaf(vA, w.y, aA1);
                aB0 = fmaf(vB, w.x, aB0);  aB1 = fmaf(vB, w.y, aB1);
            }
        }
        out[n * 112 + col0 + lane] = aA0;
        out[n2 * 112 + col0 + lane] = aB0;
        if (hasB) {
            out[n * 112 + col0 + lane + 32] = aA1;
            out[n2 * 112 + col0 + lane + 32] = aB1;
        }
    }
}

// ---------------- launch ----------------------------------------------------
extern "C" void kernel_launch(void* const* d_in, const int* in_sizes, int n_in,
                              void* d_out, int out_size) {
    const float* x     = (const float*)d_in[0];
    const int*   nidx  = (const int*)d_in[1];
    const int*   ei    = (const int*)d_in[2];
    const float* ea    = (const float*)d_in[3];
    const float* nodef = (const float*)d_in[4];
    const float* Woh   = (const float*)d_in[5];
    const float* boh   = (const float*)d_in[6];
    const float* Wne   = (const float*)d_in[7];
    const float* bne   = (const float*)d_in[8];
    const float* Wee   = (const float*)d_in[9];
    const float* bee   = (const float*)d_in[10];
    const float* lng   = (const float*)d_in[11];
    const float* lnb   = (const float*)d_in[12];
    const float* We    = (const float*)d_in[13];
    const float* be    = (const float*)d_in[14];
    const float* Wm    = (const float*)d_in[15];
    const float* bm    = (const float*)d_in[16];
    const float* lastg = (const float*)d_in[17];
    const float* lastb = (const float*)d_in[18];
    const float* Wp    = (const float*)d_in[19];
    const float* bp    = (const float*)d_in[20];
    float* out = (float*)d_out;

    const int* src = ei;
    const int* dst = ei + EE;

    k_hist<<<(EE + 255) / 256, 256>>>(dst);
    k_scan_enc_wc<<<1 + ENC_BLKS + WC_BLKS, 256>>>(x, nidx, nodef, Woh, boh,
                                                   Wne, bne, lng, lnb,
                                                   Wee, bee, We, be);
    k_scatter<<<(EE + 255) / 256, 256>>>(src, dst, (const float4*)ea);

    for (int b = 0; b < 4; b++) {
        int outoff = (b & 1) ? 64 : 0;
        const float* ng = (b < 3) ? (lng + (b + 1) * 64) : (const float*)0;
        const float* nbp = (b < 3) ? (lnb + (b + 1) * 64) : (const float*)0;
        k_aggmlp<<<NN / 8, 256>>>(b, b & 1, outoff, Wm, bm, ng, nbp);
    }

    k_final<<<1184, 256>>>(lastg, lastb, Wp, bp, out, 0);
    k_final<<<1184, 256>>>(lastg, lastb, Wp, bp, out, 56);
}

// round 11
// speedup vs baseline: 1.6824x; 1.0809x over previous
#include <cuda_runtime.h>

#define NN 100000
#define EE 1600000
#define CAP 384          // staged edges per 8-node group (mean 128)
#define ENC_BLKS 1184
#define WC_BLKS 32
#define NGRP 12500       // NN/8

// ---------------- scratch (static device globals; no allocation) ------------
__device__ float  g_h[NN * 128];       // node features, updated in place
__device__ float2 g_hblkA[NN * 32];    // ping-pong relu(LN(half)) buffers
__device__ float2 g_hblkB[NN * 32];
__device__ int    g_cnt[NN];           // zero-init; re-zeroed by scan each run
__device__ int    g_off[NN + 1];
__device__ int    g_cur[NN];
__device__ int    g_srcp[EE];          // src permuted by dst
__device__ float  g_eap[EE * 8];       // edge_attr permuted by dst
__device__ float  g_wc[4 * 8 * 64];    // folded W_ee @ We per block
__device__ float  g_bc[4 * 64];        // folded bias per block
__device__ int    g_gen;               // grid-barrier generation (monotonic)
__device__ int    g_count;             // grid-barrier counter (resets to 0)

// ---------------- histogram --------------------------------------------------
__global__ void k_hist(const int* __restrict__ dst) {
    int i = blockIdx.x * blockDim.x + threadIdx.x;
    if (i < EE) atomicAdd(&g_cnt[dst[i]], 1);
}

// ------- fused: scan (block 0) | encode+LN0 (blocks 1..1184) | wc (last 32) --
__global__ void k_scan_enc_wc(
        const float* __restrict__ x, const int* __restrict__ nidx,
        const float* __restrict__ nodef,
        const float* __restrict__ Woh, const float* __restrict__ boh,
        const float* __restrict__ Wne, const float* __restrict__ bne,
        const float* __restrict__ ln0g, const float* __restrict__ ln0b,
        const float* __restrict__ Wee, const float* __restrict__ bee,
        const float* __restrict__ We, const float* __restrict__ be) {
    __shared__ float s_woh[64], s_boh[8], s_wne[2048], s_bne[128];
    __shared__ int wsum[8];
    __shared__ int s_carry;
    int tid = threadIdx.x;
    int lane = tid & 31, wid = tid >> 5;
    int b = blockIdx.x;

    if (b == 0) {
        if (tid == 0) s_carry = 0;
        __syncthreads();
        for (int base = 0; base < NN; base += 4096) {
            int i0 = base + tid * 16;
            int v[16];
            int ts = 0;
            #pragma unroll
            for (int u = 0; u < 16; u++) {
                int i = i0 + u;
                v[u] = (i < NN) ? g_cnt[i] : 0;
                if (i < NN) g_cnt[i] = 0;
                ts += v[u];
            }
            int xv = ts;
            #pragma unroll
            for (int d = 1; d < 32; d <<= 1) {
                int t = __shfl_up_sync(0xffffffffu, xv, d);
                if (lane >= d) xv += t;
            }
            if (lane == 31) wsum[wid] = xv;
            __syncthreads();
            if (wid == 0) {
                int w = (lane < 8) ? wsum[lane] : 0;
                #pragma unroll
                for (int d = 1; d < 8; d <<= 1) {
                    int t = __shfl_up_sync(0xffffffffu, w, d);
                    if (lane >= d) w += t;
                }
                if (lane < 8) wsum[lane] = w;
            }
            __syncthreads();
            int carry = s_carry;
            int run = xv - ts + ((wid > 0) ? wsum[wid - 1] : 0) + carry;
            #pragma unroll
            for (int u = 0; u < 16; u++) {
                int i = i0 + u;
                if (i < NN) { g_off[i] = run; g_cur[i] = run; }
                run += v[u];
            }
            __syncthreads();
            if (tid == 0) s_carry = carry + wsum[7];
            __syncthreads();
        }
        if (tid == 0) g_off[NN] = s_carry;
        return;
    }
    if (b > ENC_BLKS) {
        int wcw = (b - ENC_BLKS - 1) * 8 + wid;
        for (int idx = wcw; idx < 2304; idx += WC_BLKS * 8) {
            if (idx < 2048) {
                int bb = idx >> 9, k = (idx >> 6) & 7, c = idx & 63;
                float s = 0.f;
                for (int j = lane; j < 128; j += 32)
                    s += Wee[k * 128 + j] * We[(bb * 128 + j) * 64 + c];
                #pragma unroll
                for (int d = 16; d > 0; d >>= 1) s += __shfl_xor_sync(0xffffffffu, s, d);
                if (lane == 0) g_wc[idx] = s;
            } else {
                int i2 = idx - 2048;
                int bb = i2 >> 6, c = i2 & 63;
                float s = 0.f;
                for (int j = lane; j < 128; j += 32)
                    s += bee[j] * We[(bb * 128 + j) * 64 + c];
                #pragma unroll
                for (int d = 16; d > 0; d >>= 1) s += __shfl_xor_sync(0xffffffffu, s, d);
                if (lane == 0) g_bc[i2] = be[i2] + s;
            }
        }
        return;
    }
    // ---- node encoder + fused LN/relu block 0 -> hblkA ----
    int bb = b - 1;
    for (int i = tid; i < 64; i += 256) s_woh[i] = Woh[i];
    for (int i = tid; i < 8; i += 256) s_boh[i] = boh[i];
    for (int i = tid; i < 2048; i += 256) s_wne[i] = Wne[i];
    for (int i = tid; i < 128; i += 256) s_bne[i] = bne[i];
    __syncthreads();
    int warp = bb * 8 + wid;
    int nw = ENC_BLKS * 8;
    for (int n = warp; n < NN; n += nw) {
        int s = nidx[n];
        float4 a  = *(const float4*)(nodef + s * 8);
        float4 b4 = *(const float4*)(nodef + s * 8 + 4);
        float nf1[8] = {a.x, a.y, a.z, a.w, b4.x, b4.y, b4.z, b4.w};
        float4 xa = *(const float4*)(x + n * 8);
        float4 xb = *(const float4*)(x + n * 8 + 4);
        float xv[8] = {xa.x, xa.y, xa.z, xa.w, xb.x, xb.y, xb.z, xb.w};
        float nf2[8];
        #pragma unroll
        for (int j = 0; j < 8; j++) {
            float t = s_boh[j];
            #pragma unroll
            for (int i = 0; i < 8; i++) t += xv[i] * s_woh[i * 8 + j];
            nf2[j] = t;
        }
        float acc[4];
        #pragma unroll
        for (int cc = 0; cc < 4; cc++) {
            int c = lane + cc * 32;
            float t = s_bne[c];
            #pragma unroll
            for (int k = 0; k < 8; k++) t += nf1[k] * s_wne[k * 128 + c];
            #pragma unroll
            for (int k = 0; k < 8; k++) t += nf2[k] * s_wne[(8 + k) * 128 + c];
            g_h[n * 128 + c] = t;
            acc[cc] = t;
        }
        float v0 = acc[2], v1 = acc[3];
        float su = v0 + v1, q = v0 * v0 + v1 * v1;
        #pragma unroll
        for (int d = 16; d > 0; d >>= 1) {
            su += __shfl_xor_sync(0xffffffffu, su, d);
            q  += __shfl_xor_sync(0xffffffffu, q, d);
        }
        float mu = su * (1.f / 64.f);
        float rs = rsqrtf(q * (1.f / 64.f) - mu * mu + 1e-5f);
        float r0 = fmaxf((v0 - mu) * rs * ln0g[lane] + ln0b[lane], 0.f);
        float r1 = fmaxf((v1 - mu) * rs * ln0g[lane + 32] + ln0b[lane + 32], 0.f);
        g_hblkA[n * 32 + lane] = make_float2(r0, r1);
    }
}

// ---------------- scatter edges by dst ---------------------------------------
__global__ void k_scatter(const int* __restrict__ src, const int* __restrict__ dst,
                          const float4* __restrict__ ea) {
    int i = blockIdx.x * blockDim.x + threadIdx.x;
    if (i < EE) {
        int d = dst[i];
        int pos = atomicAdd(&g_cur[d], 1);
        g_srcp[pos] = src[i];
        float4* o = (float4*)g_eap;
        o[pos * 2]     = ea[i * 2];
        o[pos * 2 + 1] = ea[i * 2 + 1];
    }
}

// ----- persistent 4-phase GEN: edges staged in smem, grid barrier between ---
// Grid = numSMs*4 blocks, all co-resident (64 regs / 30KB smem / 256 thr ->
// exactly 4 blocks per SM), so the software grid barrier cannot deadlock.
// Unshifted softmax (exact: msg bounded; weights invariant to shift/+eps;
// agg = sum(relu*w) + eps, guarded so empty nodes stay exactly 0).
__global__ void __launch_bounds__(256, 4) k_gen(
        const float* __restrict__ Wm, const float* __restrict__ bm,
        const float* __restrict__ lng, const float* __restrict__ lnb) {
    __shared__ float wms[4096];          // paired layout: (w[k][c], w[k][c+32])
    __shared__ float4 s_eap[CAP * 2];
    __shared__ int s_src[CAP];
    __shared__ int s_gen_entry;
    int tid = threadIdx.x;
    int lane = tid & 31, wid = tid >> 5;
    if (tid == 0) s_gen_entry = *(volatile int*)&g_gen;
    int nblk = gridDim.x;
    const float4* eap = (const float4*)g_eap;

    for (int phase = 0; phase < 4; phase++) {
        __syncthreads();   // prior phase done with wms; s_gen_entry visible
        // stage MLP weights (paired): wms[k*64+2c+h] = Wm[k*64 + c + h*32]
        for (int i = tid; i < 4096; i += 256) {
            int k = i >> 6, c = i & 63;
            int col = (c >> 1) + ((c & 1) << 5);
            wms[i] = Wm[phase * 4096 + k * 64 + col];
        }
        const float2* __restrict__ hin = (phase & 1) ? g_hblkB : g_hblkA;
        float2* __restrict__ hout = (phase & 1) ? g_hblkA : g_hblkB;
        int outoff = (phase & 1) ? 64 : 0;
        const float* ng = (phase < 3) ? (lng + (phase + 1) * 64) : (const float*)0;
        const float* nb = (phase < 3) ? (lnb + (phase + 1) * 64) : (const float*)0;
        const float* Wc = g_wc + phase * 512;
        float wA[8], wB[8];
        #pragma unroll
        for (int k = 0; k < 8; k++) {
            wA[k] = __ldg(&Wc[k * 64 + lane]);
            wB[k] = __ldg(&Wc[k * 64 + lane + 32]);
        }
        float bc0 = __ldg(&g_bc[phase * 64 + lane]);
        float bc1 = __ldg(&g_bc[phase * 64 + lane + 32]);
        float bm0 = __ldg(&bm[phase * 64 + lane]);
        float bm1 = __ldg(&bm[phase * 64 + lane + 32]);

        for (int grp = blockIdx.x; grp < NGRP; grp += nblk) {
            __syncthreads();   // all warps done consuming previous group's smem
            int node0 = grp * 8;
            int b0 = __ldg(&g_off[node0]);
            int bend = __ldg(&g_off[node0 + 8]);
            int staged = min(bend - b0, CAP);
            for (int j = tid; j < staged * 2; j += 256) s_eap[j] = __ldg(&eap[b0 * 2 + j]);
            for (int j = tid; j < staged; j += 256) s_src[j] = __ldg(&g_srcp[b0 + j]);
            __syncthreads();

            int node = node0 + wid;
            int e0 = __ldg(&g_off[node]), e1 = __ldg(&g_off[node + 1]);
            int l0 = e0 - b0, l1 = e1 - b0;
            int lim1 = min(l1, staged);
            float d0 = 0.f, d1 = 0.f, n0 = 0.f, n1 = 0.f;

            #define CONSUME_SMEM(l, hv)                                          \
            {                                                                    \
                float4 A = s_eap[(l) * 2];                                       \
                float4 B = s_eap[(l) * 2 + 1];                                   \
                float t0 = bc0 + (hv).x, t1 = bc1 + (hv).y;                      \
                t0 = fmaf(A.x, wA[0], t0);  t1 = fmaf(A.x, wB[0], t1);           \
                t0 = fmaf(A.y, wA[1], t0);  t1 = fmaf(A.y, wB[1], t1);           \
                t0 = fmaf(A.z, wA[2], t0);  t1 = fmaf(A.z, wB[2], t1);           \
                t0 = fmaf(A.w, wA[3], t0);  t1 = fmaf(A.w, wB[3], t1);           \
                t0 = fmaf(B.x, wA[4], t0);  t1 = fmaf(B.x, wB[4], t1);           \
                t0 = fmaf(B.y, wA[5], t0);  t1 = fmaf(B.y, wB[5], t1);           \
                t0 = fmaf(B.z, wA[6], t0);  t1 = fmaf(B.z, wB[6], t1);           \
                t0 = fmaf(B.w, wA[7], t0);  t1 = fmaf(B.w, wB[7], t1);           \
                float v0 = fmaxf(t0, 0.f);                                       \
                float v1 = fmaxf(t1, 0.f);                                       \
                float ex0 = __expf(v0);                                          \
                float ex1 = __expf(v1);                                          \
                d0 += ex0;  n0 = fmaf(v0, ex0, n0);                              \
                d1 += ex1;  n1 = fmaf(v1, ex1, n1);                              \
            }

            int l = l0;
            int rem = lim1 - l0;
            if (rem > 0) {
                float2 h0 = __ldg(&hin[s_src[l] * 32 + lane]);
                float2 h1 = (rem > 1) ? __ldg(&hin[s_src[l + 1] * 32 + lane]) : h0;
                for (; l + 2 < lim1; l++) {
                    float2 h2 = __ldg(&hin[s_src[l + 2] * 32 + lane]);
                    CONSUME_SMEM(l, h0);
                    h0 = h1;
                    h1 = h2;
                }
                if (l < lim1) { CONSUME_SMEM(l, h0); l++; }
                if (l < lim1) { CONSUME_SMEM(l, h1); l++; }
            }
            for (l = max(l0, lim1); l < l1; l++) {   // rare overflow tail
                int s = __ldg(&g_srcp[b0 + l]);
                float2 hv = __ldg(&hin[s * 32 + lane]);
                float4 A = __ldg(&eap[(b0 + l) * 2]);
                float4 B = __ldg(&eap[(b0 + l) * 2 + 1]);
                float t0 = bc0 + hv.x, t1 = bc1 + hv.y;
                t0 = fmaf(A.x, wA[0], t0);  t1 = fmaf(A.x, wB[0], t1);
                t0 = fmaf(A.y, wA[1], t0);  t1 = fmaf(A.y, wB[1], t1);
                t0 = fmaf(A.z, wA[2], t0);  t1 = fmaf(A.z, wB[2], t1);
                t0 = fmaf(A.w, wA[3], t0);  t1 = fmaf(A.w, wB[3], t1);
                t0 = fmaf(B.x, wA[4], t0);  t1 = fmaf(B.x, wB[4], t1);
                t0 = fmaf(B.y, wA[5], t0);  t1 = fmaf(B.y, wB[5], t1);
                t0 = fmaf(B.z, wA[6], t0);  t1 = fmaf(B.z, wB[6], t1);
                t0 = fmaf(B.w, wA[7], t0);  t1 = fmaf(B.w, wB[7], t1);
                float v0 = fmaxf(t0, 0.f);
                float v1 = fmaxf(t1, 0.f);
                float ex0 = __expf(v0);
                float ex1 = __expf(v1);
                d0 += ex0;  n0 = fmaf(v0, ex0, n0);
                d1 += ex1;  n1 = fmaf(v1, ex1, n1);
            }

            float2 hme = __ldg(&hin[node * 32 + lane]);
            float a0 = hme.x + ((e1 > e0) ? (n0 / d0 + 1e-7f) : 0.f);
            float a1 = hme.y + ((e1 > e0) ? (n1 / d1 + 1e-7f) : 0.f);
            // MLP: y = a @ Wm + bm (64x64 warp shfl-GEMM, paired float2 LDS)
            float acc0 = bm0, acc1 = bm1;
            const float2* wm2 = (const float2*)wms;
            #pragma unroll
            for (int k = 0; k < 32; k++) {
                float2 w = wm2[k * 32 + lane];
                float v = __shfl_sync(0xffffffffu, a0, k);
                acc0 = fmaf(v, w.x, acc0);
                acc1 = fmaf(v, w.y, acc1);
            }
            #pragma unroll
            for (int k = 0; k < 32; k++) {
                float2 w = wm2[(k + 32) * 32 + lane];
                float v = __shfl_sync(0xffffffffu, a1, k);
                acc0 = fmaf(v, w.x, acc0);
                acc1 = fmaf(v, w.y, acc1);
            }
            float* o = g_h + node * 128 + outoff;
            float y0 = o[lane] + acc0, y1 = o[lane + 32] + acc1;
            o[lane] = y0;  o[lane + 32] = y1;
            if (ng) {
                float su = y0 + y1, q = y0 * y0 + y1 * y1;
                #pragma unroll
                for (int d = 16; d > 0; d >>= 1) {
                    su += __shfl_xor_sync(0xffffffffu, su, d);
                    q  += __shfl_xor_sync(0xffffffffu, q, d);
                }
                float mu = su * (1.f / 64.f);
                float rs = rsqrtf(q * (1.f / 64.f) - mu * mu + 1e-5f);
                float r0 = fmaxf((y0 - mu) * rs * __ldg(&ng[lane]) + __ldg(&nb[lane]), 0.f);
                float r1 = fmaxf((y1 - mu) * rs * __ldg(&ng[lane + 32]) + __ldg(&nb[lane + 32]), 0.f);
                hout[node * 32 + lane] = make_float2(r0, r1);
            }
        }
        // ---- grid barrier between phases (not needed after last) ----
        if (phase < 3) {
            __syncthreads();
            if (tid == 0) {
                __threadfence();
                int t = atomicAdd(&g_count, 1);
                if (t == nblk - 1) {
                    atomicExch(&g_count, 0);
                    __threadfence();
                    atomicAdd(&g_gen, 1);
                } else {
                    while (*(volatile int*)&g_gen < s_gen_entry + phase + 1)
                        __nanosleep(64);
                }
                __threadfence();
            }
            __syncthreads();
        }
    }
}

// ---------- final: out = relu(LN(h)) @ Wp + bp, ALL 112 cols, one launch -----
// float4 weight LDS: wp4[k*32+lane] = (W[k][lane], [lane+32], [lane+64], [lane+96|0])
__global__ void k_final1(const float* __restrict__ lg, const float* __restrict__ lb,
                         const float* __restrict__ Wp, const float* __restrict__ bp,
                         float* __restrict__ out) {
    extern __shared__ float4 wp4[];     // 128*32 float4 = 64KB dynamic
    int tid = threadIdx.x;
    for (int i = tid; i < 4096; i += blockDim.x) {
        int k = i >> 5, c = i & 31;
        float w0 = Wp[k * 112 + c];
        float w1 = Wp[k * 112 + c + 32];
        float w2 = Wp[k * 112 + c + 64];
        float w3 = (c < 16) ? Wp[k * 112 + c + 96] : 0.f;
        wp4[i] = make_float4(w0, w1, w2, w3);
    }
    __syncthreads();
    int lane = tid & 31;
    int warp = blockIdx.x * (blockDim.x >> 5) + (tid >> 5);
    int nw = gridDim.x * (blockDim.x >> 5);
    bool has3 = lane < 16;
    float bp0 = bp[lane], bp1 = bp[lane + 32], bp2 = bp[lane + 64];
    float bp3 = has3 ? bp[lane + 96] : 0.f;
    float lgv[4], lbv[4];
    #pragma unroll
    for (int i = 0; i < 4; i++) { lgv[i] = lg[lane + i * 32]; lbv[i] = lb[lane + i * 32]; }
    for (int n = warp * 2; n < NN; n += nw * 2) {
        int n2 = n + 1;
        const float* hA = g_h + n * 128;
        const float* hB = g_h + n2 * 128;
        float xA[4], xB[4];
        #pragma unroll
        for (int i = 0; i < 4; i++) { xA[i] = hA[lane + i * 32]; xB[i] = hB[lane + i * 32]; }
        float sA = 0.f, qA = 0.f, sB = 0.f, qB = 0.f;
        #pragma unroll
        for (int i = 0; i < 4; i++) {
            sA += xA[i]; qA += xA[i] * xA[i];
            sB += xB[i]; qB += xB[i] * xB[i];
        }
        #pragma unroll
        for (int d = 16; d > 0; d >>= 1) {
            sA += __shfl_xor_sync(0xffffffffu, sA, d);
            qA += __shfl_xor_sync(0xffffffffu, qA, d);
            sB += __shfl_xor_sync(0xffffffffu, sB, d);
            qB += __shfl_xor_sync(0xffffffffu, qB, d);
        }
        float muA = sA * (1.f / 128.f), muB = sB * (1.f / 128.f);
        float rsA = rsqrtf(qA * (1.f / 128.f) - muA * muA + 1e-5f);
        float rsB = rsqrtf(qB * (1.f / 128.f) - muB * muB + 1e-5f);
        #pragma unroll
        for (int i = 0; i < 4; i++) {
            xA[i] = fmaxf((xA[i] - muA) * rsA * lgv[i] + lbv[i], 0.f);
            xB[i] = fmaxf((xB[i] - muB) * rsB * lgv[i] + lbv[i], 0.f);
        }
        float aA0 = bp0, aA1 = bp1, aA2 = bp2, aA3 = bp3;
        float aB0 = bp0, aB1 = bp1, aB2 = bp2, aB3 = bp3;
        #pragma unroll
        for (int i = 0; i < 4; i++) {
            #pragma unroll
            for (int k = 0; k < 32; k++) {
                float4 w = wp4[(k + i * 32) * 32 + lane];
                float vA = __shfl_sync(0xffffffffu, xA[i], k);
                float vB = __shfl_sync(0xffffffffu, xB[i], k);
                aA0 = fmaf(vA, w.x, aA0);  aA1 = fmaf(vA, w.y, aA1);
                aA2 = fmaf(vA, w.z, aA2);  aA3 = fmaf(vA, w.w, aA3);
                aB0 = fmaf(vB, w.x, aB0);  aB1 = fmaf(vB, w.y, aB1);
                aB2 = fmaf(vB, w.z, aB2);  aB3 = fmaf(vB, w.w, aB3);
            }
        }
        out[n * 112 + lane] = aA0;
        out[n * 112 + lane + 32] = aA1;
        out[n * 112 + lane + 64] = aA2;
        out[n2 * 112 + lane] = aB0;
        out[n2 * 112 + lane + 32] = aB1;
        out[n2 * 112 + lane + 64] = aB2;
        if (has3) {
            out[n * 112 + lane + 96] = aA3;
            out[n2 * 112 + lane + 96] = aB3;
        }
    }
}

// ---------------- launch ----------------------------------------------------
extern "C" void kernel_launch(void* const* d_in, const int* in_sizes, int n_in,
                              void* d_out, int out_size) {
    const float* x     = (const float*)d_in[0];
    const int*   nidx  = (const int*)d_in[1];
    const int*   ei    = (const int*)d_in[2];
    const float* ea    = (const float*)d_in[3];
    const float* nodef = (const float*)d_in[4];
    const float* Woh   = (const float*)d_in[5];
    const float* boh   = (const float*)d_in[6];
    const float* Wne   = (const float*)d_in[7];
    const float* bne   = (const float*)d_in[8];
    const float* Wee   = (const float*)d_in[9];
    const float* bee   = (const float*)d_in[10];
    const float* lng   = (const float*)d_in[11];
    const float* lnb   = (const float*)d_in[12];
    const float* We    = (const float*)d_in[13];
    const float* be    = (const float*)d_in[14];
    const float* Wm    = (const float*)d_in[15];
    const float* bm    = (const float*)d_in[16];
    const float* lastg = (const float*)d_in[17];
    const float* lastb = (const float*)d_in[18];
    const float* Wp    = (const float*)d_in[19];
    const float* bp    = (const float*)d_in[20];
    float* out = (float*)d_out;

    const int* src = ei;
    const int* dst = ei + EE;

    static int nsm = 0;
    if (nsm == 0) {
        int dev = 0;
        cudaGetDevice(&dev);
        cudaDeviceGetAttribute(&nsm, cudaDevAttrMultiProcessorCount, dev);
        cudaFuncSetAttribute(k_final1, cudaFuncAttributeMaxDynamicSharedMemorySize, 65536);
    }

    k_hist<<<(EE + 255) / 256, 256>>>(dst);
    k_scan_enc_wc<<<1 + ENC_BLKS + WC_BLKS, 256>>>(x, nidx, nodef, Woh, boh,
                                                   Wne, bne, lng, lnb,
                                                   Wee, bee, We, be);
    k_scatter<<<(EE + 255) / 256, 256>>>(src, dst, (const float4*)ea);
    k_gen<<<nsm * 4, 256>>>(Wm, bm, lng, lnb);
    k_final1<<<1184, 256, 65536>>>(lastg, lastb, Wp, bp, out);
}

// round 12
// speedup vs baseline: 1.7166x; 1.0203x over previous
#include <cuda_runtime.h>

#define NN 100000
#define EE 1600000
#define CAP 384          // staged edges per 8-node group (mean 128)
#define NGRP 12500       // NN/8

// ---------------- scratch (static device globals; no allocation) ------------
__device__ float  g_h[NN * 128];       // node features, updated in place
__device__ float2 g_hblkA[NN * 32];    // ping-pong relu(LN(half)) buffers
__device__ float2 g_hblkB[NN * 32];
__device__ int    g_cnt[NN];           // zero-init; re-zeroed each run
__device__ int    g_off[NN + 1];
__device__ int    g_cur[NN];
__device__ int    g_srcp[EE];          // src permuted by dst
__device__ float  g_eap[EE * 8];       // edge_attr permuted by dst
__device__ float  g_wc[4 * 8 * 64];    // folded W_ee @ We per block
__device__ float  g_bc[4 * 64];        // folded bias per block
__device__ int    g_part[1024];        // per-block scan partials
__device__ int    g_gen;               // grid-barrier generation (monotonic)
__device__ int    g_count;             // grid-barrier counter (resets to 0)

#define GRID_BARRIER(k)                                                       \
    __syncthreads();                                                          \
    if (tid == 0) {                                                           \
        __threadfence();                                                      \
        int t_ = atomicAdd(&g_count, 1);                                      \
        if (t_ == nblk - 1) {                                                 \
            atomicExch(&g_count, 0);                                          \
            __threadfence();                                                  \
            atomicAdd(&g_gen, 1);                                             \
        } else {                                                              \
            while (*(volatile int*)&g_gen < s_gen_entry + (k) + 1)            \
                __nanosleep(64);                                              \
        }                                                                     \
        __threadfence();                                                      \
    }                                                                         \
    __syncthreads();

// ===== persistent prep: hist+enc+wc | parallel scan | scatter ================
// Grid = numSMs*4 blocks, all co-resident (<=64 regs, small smem, 256 thr).
__global__ void __launch_bounds__(256, 4) k_prep_all(
        const int* __restrict__ src, const int* __restrict__ dst,
        const float4* __restrict__ ea,
        const float* __restrict__ x, const int* __restrict__ nidx,
        const float* __restrict__ nodef,
        const float* __restrict__ Woh, const float* __restrict__ boh,
        const float* __restrict__ Wne, const float* __restrict__ bne,
        const float* __restrict__ ln0g, const float* __restrict__ ln0b,
        const float* __restrict__ Wee, const float* __restrict__ bee,
        const float* __restrict__ We, const float* __restrict__ be) {
    __shared__ float s_woh[64], s_boh[8], s_wne[2048], s_bne[128];
    __shared__ int s_excl[256];
    __shared__ int s_wtot[8];
    __shared__ int s_gen_entry;
    int tid = threadIdx.x, lane = tid & 31, wid = tid >> 5;
    int nblk = gridDim.x, b = blockIdx.x;
    if (tid == 0) s_gen_entry = *(volatile int*)&g_gen;

    // ---------------- Phase A: hist + wc + encode(+LN0) ----------------
    for (int i = b * 256 + tid; i < EE; i += nblk * 256)
        atomicAdd(&g_cnt[dst[i]], 1);
    int gw = b * 8 + wid;
    // wc: warp per output (2304 outputs)
    for (int idx = gw; idx < 2304; idx += nblk * 8) {
        if (idx < 2048) {
            int bb = idx >> 9, k = (idx >> 6) & 7, c = idx & 63;
            float s = 0.f;
            for (int j = lane; j < 128; j += 32)
                s += Wee[k * 128 + j] * We[(bb * 128 + j) * 64 + c];
            #pragma unroll
            for (int d = 16; d > 0; d >>= 1) s += __shfl_xor_sync(0xffffffffu, s, d);
            if (lane == 0) g_wc[idx] = s;
        } else {
            int i2 = idx - 2048;
            int bb = i2 >> 6, c = i2 & 63;
            float s = 0.f;
            for (int j = lane; j < 128; j += 32)
                s += bee[j] * We[(bb * 128 + j) * 64 + c];
            #pragma unroll
            for (int d = 16; d > 0; d >>= 1) s += __shfl_xor_sync(0xffffffffu, s, d);
            if (lane == 0) g_bc[i2] = be[i2] + s;
        }
    }
    // encode
    for (int i = tid; i < 64; i += 256) s_woh[i] = Woh[i];
    for (int i = tid; i < 8; i += 256) s_boh[i] = boh[i];
    for (int i = tid; i < 2048; i += 256) s_wne[i] = Wne[i];
    for (int i = tid; i < 128; i += 256) s_bne[i] = bne[i];
    __syncthreads();
    for (int n = gw; n < NN; n += nblk * 8) {
        int s = nidx[n];
        float4 a  = *(const float4*)(nodef + s * 8);
        float4 b4 = *(const float4*)(nodef + s * 8 + 4);
        float nf1[8] = {a.x, a.y, a.z, a.w, b4.x, b4.y, b4.z, b4.w};
        float4 xa = *(const float4*)(x + n * 8);
        float4 xb = *(const float4*)(x + n * 8 + 4);
        float xv[8] = {xa.x, xa.y, xa.z, xa.w, xb.x, xb.y, xb.z, xb.w};
        float nf2[8];
        #pragma unroll
        for (int j = 0; j < 8; j++) {
            float t = s_boh[j];
            #pragma unroll
            for (int i = 0; i < 8; i++) t += xv[i] * s_woh[i * 8 + j];
            nf2[j] = t;
        }
        float acc[4];
        #pragma unroll
        for (int cc = 0; cc < 4; cc++) {
            int c = lane + cc * 32;
            float t = s_bne[c];
            #pragma unroll
            for (int k = 0; k < 8; k++) t += nf1[k] * s_wne[k * 128 + c];
            #pragma unroll
            for (int k = 0; k < 8; k++) t += nf2[k] * s_wne[(8 + k) * 128 + c];
            g_h[n * 128 + c] = t;
            acc[cc] = t;
        }
        float v0 = acc[2], v1 = acc[3];
        float su = v0 + v1, q = v0 * v0 + v1 * v1;
        #pragma unroll
        for (int d = 16; d > 0; d >>= 1) {
            su += __shfl_xor_sync(0xffffffffu, su, d);
            q  += __shfl_xor_sync(0xffffffffu, q, d);
        }
        float mu = su * (1.f / 64.f);
        float rs = rsqrtf(q * (1.f / 64.f) - mu * mu + 1e-5f);
        float r0 = fmaxf((v0 - mu) * rs * ln0g[lane] + ln0b[lane], 0.f);
        float r1 = fmaxf((v1 - mu) * rs * ln0g[lane + 32] + ln0b[lane + 32], 0.f);
        g_hblkA[n * 32 + lane] = make_float2(r0, r1);
    }

    GRID_BARRIER(0)

    // ---------------- Phase B1: block-local scan of tile ----------------
    int TILE = (NN + nblk - 1) / nblk;          // <=256 for nblk>=391
    int i0 = b * TILE;
    int cnt = NN - i0;
    if (cnt > TILE) cnt = TILE;
    if (cnt < 0) cnt = 0;
    int v = (tid < cnt) ? g_cnt[i0 + tid] : 0;
    int xv = v;
    #pragma unroll
    for (int d = 1; d < 32; d <<= 1) {
        int t = __shfl_up_sync(0xffffffffu, xv, d);
        if (lane >= d) xv += t;
    }
    if (lane == 31) s_wtot[wid] = xv;
    __syncthreads();
    if (wid == 0) {
        int w = (lane < 8) ? s_wtot[lane] : 0;
        #pragma unroll
        for (int d = 1; d < 8; d <<= 1) {
            int t = __shfl_up_sync(0xffffffffu, w, d);
            if (lane >= d) w += t;
        }
        if (lane < 8) s_wtot[lane] = w;
    }
    __syncthreads();
    s_excl[tid] = xv - v + ((wid > 0) ? s_wtot[wid - 1] : 0);
    if (tid == 0) g_part[b] = s_wtot[7];

    GRID_BARRIER(1)

    // ---------------- Phase B2: block 0 scans the partials ----------------
    if (b == 0 && wid == 0) {
        int carry = 0;
        for (int base = 0; base < nblk; base += 32) {
            int i = base + lane;
            int pv = (i < nblk) ? g_part[i] : 0;
            int px = pv;
            #pragma unroll
            for (int d = 1; d < 32; d <<= 1) {
                int t = __shfl_up_sync(0xffffffffu, px, d);
                if (lane >= d) px += t;
            }
            if (i < nblk) g_part[i] = px - pv + carry;
            carry += __shfl_sync(0xffffffffu, px, 31);
        }
        if (lane == 0) g_off[NN] = EE;
    }

    GRID_BARRIER(2)

    // ---------------- Phase B3: apply + rezero ----------------
    {
        int basep = g_part[b];
        if (tid < cnt) {
            int o = basep + s_excl[tid];
            g_off[i0 + tid] = o;
            g_cur[i0 + tid] = o;
            g_cnt[i0 + tid] = 0;
        }
    }

    GRID_BARRIER(3)

    // ---------------- Phase C: scatter ----------------
    for (int i = b * 256 + tid; i < EE; i += nblk * 256) {
        int d = dst[i];
        int pos = atomicAdd(&g_cur[d], 1);
        g_srcp[pos] = src[i];
        float4* o = (float4*)g_eap;
        o[pos * 2]     = ea[i * 2];
        o[pos * 2 + 1] = ea[i * 2 + 1];
    }
}

// ----- persistent 4-phase GEN: edges staged in smem, grid barrier between ---
// Grid = numSMs*4 blocks, all co-resident (64 regs / 30KB smem / 256 thr).
// Unshifted softmax (exact: msg bounded; weights invariant to shift/+eps;
// agg = sum(relu*w) + eps, guarded so empty nodes stay exactly 0).
__global__ void __launch_bounds__(256, 4) k_gen(
        const float* __restrict__ Wm, const float* __restrict__ bm,
        const float* __restrict__ lng, const float* __restrict__ lnb) {
    __shared__ float wms[4096];          // paired layout: (w[k][c], w[k][c+32])
    __shared__ float4 s_eap[CAP * 2];
    __shared__ int s_src[CAP];
    __shared__ int s_gen_entry;
    int tid = threadIdx.x;
    int lane = tid & 31, wid = tid >> 5;
    if (tid == 0) s_gen_entry = *(volatile int*)&g_gen;
    int nblk = gridDim.x;
    const float4* eap = (const float4*)g_eap;

    for (int phase = 0; phase < 4; phase++) {
        __syncthreads();
        for (int i = tid; i < 4096; i += 256) {
            int k = i >> 6, c = i & 63;
            int col = (c >> 1) + ((c & 1) << 5);
            wms[i] = Wm[phase * 4096 + k * 64 + col];
        }
        const float2* __restrict__ hin = (phase & 1) ? g_hblkB : g_hblkA;
        float2* __restrict__ hout = (phase & 1) ? g_hblkA : g_hblkB;
        int outoff = (phase & 1) ? 64 : 0;
        const float* ng = (phase < 3) ? (lng + (phase + 1) * 64) : (const float*)0;
        const float* nb = (phase < 3) ? (lnb + (phase + 1) * 64) : (const float*)0;
        const float* Wc = g_wc + phase * 512;
        float wA[8], wB[8];
        #pragma unroll
        for (int k = 0; k < 8; k++) {
            wA[k] = __ldg(&Wc[k * 64 + lane]);
            wB[k] = __ldg(&Wc[k * 64 + lane + 32]);
        }
        float bc0 = __ldg(&g_bc[phase * 64 + lane]);
        float bc1 = __ldg(&g_bc[phase * 64 + lane + 32]);
        float bm0 = __ldg(&bm[phase * 64 + lane]);
        float bm1 = __ldg(&bm[phase * 64 + lane + 32]);

        for (int grp = blockIdx.x; grp < NGRP; grp += nblk) {
            __syncthreads();
            int node0 = grp * 8;
            int b0 = __ldg(&g_off[node0]);
            int bend = __ldg(&g_off[node0 + 8]);
            int staged = min(bend - b0, CAP);
            for (int j = tid; j < staged * 2; j += 256) s_eap[j] = __ldg(&eap[b0 * 2 + j]);
            for (int j = tid; j < staged; j += 256) s_src[j] = __ldg(&g_srcp[b0 + j]);
            __syncthreads();

            int node = node0 + wid;
            int e0 = __ldg(&g_off[node]), e1 = __ldg(&g_off[node + 1]);
            int l0 = e0 - b0, l1 = e1 - b0;
            int lim1 = min(l1, staged);
            float d0 = 0.f, d1 = 0.f, n0 = 0.f, n1 = 0.f;

            #define CONSUME_SMEM(l, hv)                                          \
            {                                                                    \
                float4 A = s_eap[(l) * 2];                                       \
                float4 B = s_eap[(l) * 2 + 1];                                   \
                float t0 = bc0 + (hv).x, t1 = bc1 + (hv).y;                      \
                t0 = fmaf(A.x, wA[0], t0);  t1 = fmaf(A.x, wB[0], t1);           \
                t0 = fmaf(A.y, wA[1], t0);  t1 = fmaf(A.y, wB[1], t1);           \
                t0 = fmaf(A.z, wA[2], t0);  t1 = fmaf(A.z, wB[2], t1);           \
                t0 = fmaf(A.w, wA[3], t0);  t1 = fmaf(A.w, wB[3], t1);           \
                t0 = fmaf(B.x, wA[4], t0);  t1 = fmaf(B.x, wB[4], t1);           \
                t0 = fmaf(B.y, wA[5], t0);  t1 = fmaf(B.y, wB[5], t1);           \
                t0 = fmaf(B.z, wA[6], t0);  t1 = fmaf(B.z, wB[6], t1);           \
                t0 = fmaf(B.w, wA[7], t0);  t1 = fmaf(B.w, wB[7], t1);           \
                float v0 = fmaxf(t0, 0.f);                                       \
                float v1 = fmaxf(t1, 0.f);                                       \
                float ex0 = __expf(v0);                                          \
                float ex1 = __expf(v1);                                          \
                d0 += ex0;  n0 = fmaf(v0, ex0, n0);                              \
                d1 += ex1;  n1 = fmaf(v1, ex1, n1);                              \
            }

            int l = l0;
            int rem = lim1 - l0;
            if (rem > 0) {
                float2 h0 = __ldg(&hin[s_src[l] * 32 + lane]);
                float2 h1 = (rem > 1) ? __ldg(&hin[s_src[l + 1] * 32 + lane]) : h0;
                for (; l + 2 < lim1; l++) {
                    float2 h2 = __ldg(&hin[s_src[l + 2] * 32 + lane]);
                    CONSUME_SMEM(l, h0);
                    h0 = h1;
                    h1 = h2;
                }
                if (l < lim1) { CONSUME_SMEM(l, h0); l++; }
                if (l < lim1) { CONSUME_SMEM(l, h1); l++; }
            }
            for (l = max(l0, lim1); l < l1; l++) {   // rare overflow tail
                int s = __ldg(&g_srcp[b0 + l]);
                float2 hv = __ldg(&hin[s * 32 + lane]);
                float4 A = __ldg(&eap[(b0 + l) * 2]);
                float4 B = __ldg(&eap[(b0 + l) * 2 + 1]);
                float t0 = bc0 + hv.x, t1 = bc1 + hv.y;
                t0 = fmaf(A.x, wA[0], t0);  t1 = fmaf(A.x, wB[0], t1);
                t0 = fmaf(A.y, wA[1], t0);  t1 = fmaf(A.y, wB[1], t1);
                t0 = fmaf(A.z, wA[2], t0);  t1 = fmaf(A.z, wB[2], t1);
                t0 = fmaf(A.w, wA[3], t0);  t1 = fmaf(A.w, wB[3], t1);
                t0 = fmaf(B.x, wA[4], t0);  t1 = fmaf(B.x, wB[4], t1);
                t0 = fmaf(B.y, wA[5], t0);  t1 = fmaf(B.y, wB[5], t1);
                t0 = fmaf(B.z, wA[6], t0);  t1 = fmaf(B.z, wB[6], t1);
                t0 = fmaf(B.w, wA[7], t0);  t1 = fmaf(B.w, wB[7], t1);
                float v0 = fmaxf(t0, 0.f);
                float v1 = fmaxf(t1, 0.f);
                float ex0 = __expf(v0);
                float ex1 = __expf(v1);
                d0 += ex0;  n0 = fmaf(v0, ex0, n0);
                d1 += ex1;  n1 = fmaf(v1, ex1, n1);
            }

            float2 hme = __ldg(&hin[node * 32 + lane]);
            float a0 = hme.x + ((e1 > e0) ? (n0 / d0 + 1e-7f) : 0.f);
            float a1 = hme.y + ((e1 > e0) ? (n1 / d1 + 1e-7f) : 0.f);
            float acc0 = bm0, acc1 = bm1;
            const float2* wm2 = (const float2*)wms;
            #pragma unroll
            for (int k = 0; k < 32; k++) {
                float2 w = wm2[k * 32 + lane];
                float v = __shfl_sync(0xffffffffu, a0, k);
                acc0 = fmaf(v, w.x, acc0);
                acc1 = fmaf(v, w.y, acc1);
            }
            #pragma unroll
            for (int k = 0; k < 32; k++) {
                float2 w = wm2[(k + 32) * 32 + lane];
                float v = __shfl_sync(0xffffffffu, a1, k);
                acc0 = fmaf(v, w.x, acc0);
                acc1 = fmaf(v, w.y, acc1);
            }
            float* o = g_h + node * 128 + outoff;
            float y0 = o[lane] + acc0, y1 = o[lane + 32] + acc1;
            o[lane] = y0;  o[lane + 32] = y1;
            if (ng) {
                float su = y0 + y1, q = y0 * y0 + y1 * y1;
                #pragma unroll
                for (int d = 16; d > 0; d >>= 1) {
                    su += __shfl_xor_sync(0xffffffffu, su, d);
                    q  += __shfl_xor_sync(0xffffffffu, q, d);
                }
                float mu = su * (1.f / 64.f);
                float rs = rsqrtf(q * (1.f / 64.f) - mu * mu + 1e-5f);
                float r0 = fmaxf((y0 - mu) * rs * __ldg(&ng[lane]) + __ldg(&nb[lane]), 0.f);
                float r1 = fmaxf((y1 - mu) * rs * __ldg(&ng[lane + 32]) + __ldg(&nb[lane + 32]), 0.f);
                hout[node * 32 + lane] = make_float2(r0, r1);
            }
        }
        if (phase < 3) {
            GRID_BARRIER(phase)
        }
    }
}

// ---------- final: out = relu(LN(h)) @ Wp + bp, ALL 112 cols, one launch -----
__global__ void k_final1(const float* __restrict__ lg, const float* __restrict__ lb,
                         const float* __restrict__ Wp, const float* __restrict__ bp,
                         float* __restrict__ out) {
    extern __shared__ float4 wp4[];     // 128*32 float4 = 64KB dynamic
    int tid = threadIdx.x;
    for (int i = tid; i < 4096; i += blockDim.x) {
        int k = i >> 5, c = i & 31;
        float w0 = Wp[k * 112 + c];
        float w1 = Wp[k * 112 + c + 32];
        float w2 = Wp[k * 112 + c + 64];
        float w3 = (c < 16) ? Wp[k * 112 + c + 96] : 0.f;
        wp4[i] = make_float4(w0, w1, w2, w3);
    }
    __syncthreads();
    int lane = tid & 31;
    int warp = blockIdx.x * (blockDim.x >> 5) + (tid >> 5);
    int nw = gridDim.x * (blockDim.x >> 5);
    bool has3 = lane < 16;
    float bp0 = bp[lane], bp1 = bp[lane + 32], bp2 = bp[lane + 64];
    float bp3 = has3 ? bp[lane + 96] : 0.f;
    float lgv[4], lbv[4];
    #pragma unroll
    for (int i = 0; i < 4; i++) { lgv[i] = lg[lane + i * 32]; lbv[i] = lb[lane + i * 32]; }
    for (int n = warp * 2; n < NN; n += nw * 2) {
        int n2 = n + 1;
        const float* hA = g_h + n * 128;
        const float* hB = g_h + n2 * 128;
        float xA[4], xB[4];
        #pragma unroll
        for (int i = 0; i < 4; i++) { xA[i] = hA[lane + i * 32]; xB[i] = hB[lane + i * 32]; }
        float sA = 0.f, qA = 0.f, sB = 0.f, qB = 0.f;
        #pragma unroll
        for (int i = 0; i < 4; i++) {
            sA += xA[i]; qA += xA[i] * xA[i];
            sB += xB[i]; qB += xB[i] * xB[i];
        }
        #pragma unroll
        for (int d = 16; d > 0; d >>= 1) {
            sA += __shfl_xor_sync(0xffffffffu, sA, d);
            qA += __shfl_xor_sync(0xffffffffu, qA, d);
            sB += __shfl_xor_sync(0xffffffffu, sB, d);
            qB += __shfl_xor_sync(0xffffffffu, qB, d);
        }
        float muA = sA * (1.f / 128.f), muB = sB * (1.f / 128.f);
        float rsA = rsqrtf(qA * (1.f / 128.f) - muA * muA + 1e-5f);
        float rsB = rsqrtf(qB * (1.f / 128.f) - muB * muB + 1e-5f);
        #pragma unroll
        for (int i = 0; i < 4; i++) {
            xA[i] = fmaxf((xA[i] - muA) * rsA * lgv[i] + lbv[i], 0.f);
            xB[i] = fmaxf((xB[i] - muB) * rsB * lgv[i] + lbv[i], 0.f);
        }
        float aA0 = bp0, aA1 = bp1, aA2 = bp2, aA3 = bp3;
        float aB0 = bp0, aB1 = bp1, aB2 = bp2, aB3 = bp3;
        #pragma unroll
        for (int i = 0; i < 4; i++) {
            #pragma unroll
            for (int k = 0; k < 32; k++) {
                float4 w = wp4[(k + i * 32) * 32 + lane];
                float vA = __shfl_sync(0xffffffffu, xA[i], k);
                float vB = __shfl_sync(0xffffffffu, xB[i], k);
                aA0 = fmaf(vA, w.x, aA0);  aA1 = fmaf(vA, w.y, aA1);
                aA2 = fmaf(vA, w.z, aA2);  aA3 = fmaf(vA, w.w, aA3);
                aB0 = fmaf(vB, w.x, aB0);  aB1 = fmaf(vB, w.y, aB1);
                aB2 = fmaf(vB, w.z, aB2);  aB3 = fmaf(vB, w.w, aB3);
            }
        }
        out[n * 112 + lane] = aA0;
        out[n * 112 + lane + 32] = aA1;
        out[n * 112 + lane + 64] = aA2;
        out[n2 * 112 + lane] = aB0;
        out[n2 * 112 + lane + 32] = aB1;
        out[n2 * 112 + lane + 64] = aB2;
        if (has3) {
            out[n * 112 + lane + 96] = aA3;
            out[n2 * 112 + lane + 96] = aB3;
        }
    }
}

// ---------------- launch ----------------------------------------------------
extern "C" void kernel_launch(void* const* d_in, const int* in_sizes, int n_in,
                              void* d_out, int out_size) {
    const float* x     = (const float*)d_in[0];
    const int*   nidx  = (const int*)d_in[1];
    const int*   ei    = (const int*)d_in[2];
    const float* ea    = (const float*)d_in[3];
    const float* nodef = (const float*)d_in[4];
    const float* Woh   = (const float*)d_in[5];
    const float* boh   = (const float*)d_in[6];
    const float* Wne   = (const float*)d_in[7];
    const float* bne   = (const float*)d_in[8];
    const float* Wee   = (const float*)d_in[9];
    const float* bee   = (const float*)d_in[10];
    const float* lng   = (const float*)d_in[11];
    const float* lnb   = (const float*)d_in[12];
    const float* We    = (const float*)d_in[13];
    const float* be    = (const float*)d_in[14];
    const float* Wm    = (const float*)d_in[15];
    const float* bm    = (const float*)d_in[16];
    const float* lastg = (const float*)d_in[17];
    const float* lastb = (const float*)d_in[18];
    const float* Wp    = (const float*)d_in[19];
    const float* bp    = (const float*)d_in[20];
    float* out = (float*)d_out;

    const int* src = ei;
    const int* dst = ei + EE;

    static int nsm = 0;
    if (nsm == 0) {
        int dev = 0;
        cudaGetDevice(&dev);
        cudaDeviceGetAttribute(&nsm, cudaDevAttrMultiProcessorCount, dev);
        cudaFuncSetAttribute(k_final1, cudaFuncAttributeMaxDynamicSharedMemorySize, 65536);
    }

    k_prep_all<<<nsm * 4, 256>>>(src, dst, (const float4*)ea,
                                 x, nidx, nodef, Woh, boh, Wne, bne,
                                 lng, lnb, Wee, bee, We, be);
    k_gen<<<nsm * 4, 256>>>(Wm, bm, lng, lnb);
    k_final1<<<nsm * 3, 256, 65536>>>(lastg, lastb, Wp, bp, out);
}